// round 12
// baseline (speedup 1.0000x reference)
#include <cuda_runtime.h>
#include <cuda_fp16.h>
#include <cstdint>
#include <math.h>

#define T_NODES 16384
#define DIM     1024
#define NHEAD   16
#define HD      64
#define NGRAPH  32
#define NPG     512

// ---------------- scratch (device globals) ----------------
__device__ __half g_h_h  [(size_t)T_NODES * DIM];
__device__ __half g_qkv_h[(size_t)T_NODES * 3 * DIM];
__device__ __half g_attn_h[(size_t)T_NODES * DIM];
__device__ __half g_x1_h [(size_t)T_NODES * DIM];
__device__ __half g_f1_h [(size_t)T_NODES * 2 * DIM];
__device__ __half g_win_h [3 * DIM * DIM];
__device__ __half g_wout_h[DIM * DIM];
__device__ __half g_fw1_h [2 * DIM * DIM];
__device__ __half g_fw2_h [2 * DIM * DIM];
__device__ float  g_tmp[(size_t)T_NODES * DIM];
__device__ float  g_x1 [(size_t)T_NODES * DIM];

// ---------------- helpers ----------------
__device__ __forceinline__ uint32_t smem_u32(const void* p) {
    uint32_t a;
    asm("{ .reg .u64 t; cvta.to.shared.u64 t, %1; cvt.u32.u64 %0, t; }" : "=r"(a) : "l"(p));
    return a;
}
__device__ __forceinline__ void mma_f16(float* c, const uint32_t* a, const uint32_t* b) {
    asm volatile(
        "mma.sync.aligned.m16n8k16.row.col.f32.f16.f16.f32 "
        "{%0,%1,%2,%3}, {%4,%5,%6,%7}, {%8,%9}, {%0,%1,%2,%3};"
        : "+f"(c[0]), "+f"(c[1]), "+f"(c[2]), "+f"(c[3])
        : "r"(a[0]), "r"(a[1]), "r"(a[2]), "r"(a[3]), "r"(b[0]), "r"(b[1]));
}
__device__ __forceinline__ void ldsm4(uint32_t& r0, uint32_t& r1, uint32_t& r2,
                                      uint32_t& r3, uint32_t addr) {
    asm volatile("ldmatrix.sync.aligned.m8n8.x4.shared.b16 {%0,%1,%2,%3}, [%4];"
                 : "=r"(r0), "=r"(r1), "=r"(r2), "=r"(r3) : "r"(addr));
}
__device__ __forceinline__ void ldsm4t(uint32_t& r0, uint32_t& r1, uint32_t& r2,
                                       uint32_t& r3, uint32_t addr) {
    asm volatile("ldmatrix.sync.aligned.m8n8.x4.trans.shared.b16 {%0,%1,%2,%3}, [%4];"
                 : "=r"(r0), "=r"(r1), "=r"(r2), "=r"(r3) : "r"(addr));
}
__device__ __forceinline__ void cp16(uint32_t dst, const void* src) {
    asm volatile("cp.async.cg.shared.global [%0], [%1], 16;" :: "r"(dst), "l"(src));
}
__device__ __forceinline__ void cp_commit() { asm volatile("cp.async.commit_group;"); }
template <int N>
__device__ __forceinline__ void cp_wait() {
    asm volatile("cp.async.wait_group %0;" :: "n"(N));
}

// ---------------- fused fp32 -> fp16 converts (one launch) ----------------
#define CN0 (T_NODES * DIM / 4)
#define CN1 (3 * DIM * DIM / 4)
#define CN2 (DIM * DIM / 4)
#define CN3 (2 * DIM * DIM / 4)
#define CN4 (2 * DIM * DIM / 4)
#define CNT (CN0 + CN1 + CN2 + CN3 + CN4)

__global__ void __launch_bounds__(256) f32_to_f16_all(
    const float* __restrict__ a0, __half* __restrict__ b0,
    const float* __restrict__ a1, __half* __restrict__ b1,
    const float* __restrict__ a2, __half* __restrict__ b2,
    const float* __restrict__ a3, __half* __restrict__ b3,
    const float* __restrict__ a4, __half* __restrict__ b4)
{
    int i = blockIdx.x * 256 + threadIdx.x;
    if (i >= CNT) return;
    const float* s; __half* d; int off;
    if (i < CN0)                       { s = a0; d = b0; off = i; }
    else if (i < CN0 + CN1)            { s = a1; d = b1; off = i - CN0; }
    else if (i < CN0 + CN1 + CN2)      { s = a2; d = b2; off = i - CN0 - CN1; }
    else if (i < CN0 + CN1 + CN2 + CN3){ s = a3; d = b3; off = i - CN0 - CN1 - CN2; }
    else                               { s = a4; d = b4; off = i - CN0 - CN1 - CN2 - CN3; }
    float4 v = ((const float4*)s)[off];
    __half2 x = __floats2half2_rn(v.x, v.y);
    __half2 y = __floats2half2_rn(v.z, v.w);
    uint2 u; u.x = *(uint32_t*)&x; u.y = *(uint32_t*)&y;
    ((uint2*)d)[off] = u;
}

// ============================ fp16 mma GEMM v5 ============================
// 128x128 CTA tile, warp tile 64x32, BK=64, ldmatrix fragments,
// 3-slot cp.async pipeline, 2 CTAs/SM, CHUNK-PHASE STAGGERED across CTAs.
#define BM 128
#define BN 128
#define BKH 64
#define A_BYTES (BM * 128)                      // 16384
#define B_BYTES (BN * 128)                      // 16384
#define SLOT_BYTES (A_BYTES + B_BYTES)          // 32768
#define NSLOT 3
#define GEMM_SMEM (NSLOT * SLOT_BYTES + 512)    // 98816 -> 2 CTAs/SM

template <bool RELU, bool OUTH>
__global__ void __launch_bounds__(256, 2) gemm_h(
    const __half* __restrict__ A, const __half* __restrict__ B,
    const float* __restrict__ bias, float* __restrict__ Cf,
    __half* __restrict__ Ch, int M, int N, int K)
{
    extern __shared__ char smem[];
    const uint32_t sbase = smem_u32(smem);
    float* sbias = (float*)(smem + NSLOT * SLOT_BYTES);

    const int tid = threadIdx.x;
    const int wid = tid >> 5, lane = tid & 31;
    const int g = lane >> 2, t = lane & 3;
    const int wm = wid & 1, wn = wid >> 1;
    const int m0 = blockIdx.y * BM, n0 = blockIdx.x * BN;

    if (tid < BN) sbias[tid] = bias[n0 + tid];

    // ldmatrix per-thread addressing
    const int lrow = lane & 15;
    const int lsel = lane >> 4;
    const int lxor = lane & 7;
    uint32_t aoff[4], boff[2];
#pragma unroll
    for (int mt = 0; mt < 4; mt++)
        aoff[mt] = (wm * 64 + mt * 16 + lrow) * 128;
#pragma unroll
    for (int pr = 0; pr < 2; pr++)
        boff[pr] = A_BYTES + (wn * 32 + pr * 16 + lrow) * 128;
    uint32_t cbv[4];
#pragma unroll
    for (int ks = 0; ks < 4; ks++)
        cbv[ks] = (uint32_t)(((2 * ks + lsel) ^ lxor) << 4);

    float acc[4][4][4];
#pragma unroll
    for (int i = 0; i < 4; i++)
#pragma unroll
        for (int j = 0; j < 4; j++)
#pragma unroll
            for (int q = 0; q < 4; q++) acc[i][j][q] = 0.f;

    const int NC = K / BKH;
    // phase stagger: co-resident CTAs start a half-period apart
    const int cstart = ((blockIdx.x + blockIdx.y) & 1) * (NC >> 1);

    auto loadc = [&](int c, int slot) {
        const uint32_t sA = sbase + slot * SLOT_BYTES;
        const uint32_t sB = sA + A_BYTES;
        const __half* Ab = A + (size_t)m0 * K + c * BKH;
        const __half* Bb = B + (size_t)n0 * K + c * BKH;
#pragma unroll
        for (int i = 0; i < 4; i++) {
            int idx = tid + i * 256;
            int r = idx >> 3, ch = idx & 7;
            cp16(sA + r * 128 + ((ch ^ (r & 7)) << 4), Ab + (size_t)r * K + ch * 8);
        }
#pragma unroll
        for (int i = 0; i < 4; i++) {
            int idx = tid + i * 256;
            int r = idx >> 3, ch = idx & 7;
            cp16(sB + r * 128 + ((ch ^ (r & 7)) << 4), Bb + (size_t)r * K + ch * 8);
        }
    };

    {
        int c1 = cstart + 1; if (c1 >= NC) c1 -= NC;
        loadc(cstart, 0); cp_commit();
        loadc(c1, 1); cp_commit();
    }

    int slot = 0;
    int c = cstart;
    for (int i = 0; i < NC; i++) {
        cp_wait<1>();
        __syncthreads();
        int nslot = slot + 2; if (nslot >= NSLOT) nslot -= NSLOT;
        if (i + 2 < NC) {
            int cl = c + 2; if (cl >= NC) cl -= NC;
            loadc(cl, nslot);
        }
        cp_commit();

        const uint32_t slotb = sbase + slot * SLOT_BYTES;
#pragma unroll
        for (int ks = 0; ks < 4; ks++) {
            const uint32_t cb = cbv[ks];
            uint32_t af[4][4];
#pragma unroll
            for (int mt = 0; mt < 4; mt++)
                ldsm4(af[mt][0], af[mt][1], af[mt][2], af[mt][3],
                      slotb + aoff[mt] + cb);
            uint32_t bf[4][2];
#pragma unroll
            for (int pr = 0; pr < 2; pr++) {
                uint32_t r0, r1, r2, r3;
                ldsm4(r0, r1, r2, r3, slotb + boff[pr] + cb);
                bf[2 * pr][0] = r0; bf[2 * pr][1] = r2;
                bf[2 * pr + 1][0] = r1; bf[2 * pr + 1][1] = r3;
            }
#pragma unroll
            for (int mt = 0; mt < 4; mt++)
#pragma unroll
                for (int nt = 0; nt < 4; nt++)
                    mma_f16(acc[mt][nt], af[mt], bf[nt]);
        }
        if (++slot >= NSLOT) slot = 0;
        if (++c >= NC) c = 0;
    }

    // epilogue
#pragma unroll
    for (int mt = 0; mt < 4; mt++) {
        const int row = m0 + wm * 64 + mt * 16 + g;
#pragma unroll
        for (int nt = 0; nt < 4; nt++) {
            const int cc = wn * 32 + nt * 8 + 2 * t;
            float b0 = sbias[cc], b1 = sbias[cc + 1];
            float r00 = acc[mt][nt][0] + b0, r01 = acc[mt][nt][1] + b1;
            float r10 = acc[mt][nt][2] + b0, r11 = acc[mt][nt][3] + b1;
            if (RELU) {
                r00 = fmaxf(r00, 0.f); r01 = fmaxf(r01, 0.f);
                r10 = fmaxf(r10, 0.f); r11 = fmaxf(r11, 0.f);
            }
            if (OUTH) {
                __half2 h0 = __floats2half2_rn(r00, r01);
                __half2 h1 = __floats2half2_rn(r10, r11);
                *(__half2*)(Ch + (size_t)row * N + n0 + cc) = h0;
                *(__half2*)(Ch + (size_t)(row + 8) * N + n0 + cc) = h1;
            } else {
                float2 v0 = {r00, r01}, v1 = {r10, r11};
                *(float2*)(Cf + (size_t)row * N + n0 + cc) = v0;
                *(float2*)(Cf + (size_t)(row + 8) * N + n0 + cc) = v1;
            }
        }
    }
}

// ============================ attention (R9 winner, unchanged) =====================
#define SSTH2 260
#define S_BYTES (64 * SSTH2 * 4)
#define QKSTR 36
#define QOFF S_BYTES
#define KOFF (QOFF + 64 * QKSTR * 4)
#define ATTN_SMEM (KOFF + 64 * QKSTR * 4)

__global__ void __launch_bounds__(256, 2) attn_mma(
    const __half* __restrict__ qkvh, __half* __restrict__ oh)
{
    extern __shared__ char smc[];
    __half2* Sh2 = (__half2*)smc;
    uint32_t* Qw = (uint32_t*)(smc + QOFF);
    uint32_t* Kw = (uint32_t*)(smc + KOFF);
    __half* Vh = (__half*)(smc + QOFF);
    const uint32_t sb = smem_u32(smc);

    const int tid = threadIdx.x;
    const int wid = tid >> 5, lane = tid & 31;
    const int g = lane >> 2, t = lane & 3;
    const int wq = wid & 1, wk = wid >> 1;
    const int qt = blockIdx.x, hh = blockIdx.y, gg = blockIdx.z;
    const size_t nb = (size_t)gg * NPG;

    const int lr = tid >> 3, lch = tid & 7;
#pragma unroll
    for (int i = 0; i < 2; i++) {
        int r = lr + i * 32;
        uint4 v = *(const uint4*)(qkvh + (nb + qt * 64 + r) * 3072 + hh * 64 + lch * 8);
        *(uint4*)(Qw + r * QKSTR + lch * 4) = v;
    }
    uint4 kreg[2];
#pragma unroll
    for (int i = 0; i < 2; i++) {
        int r = lr + i * 32;
        kreg[i] = *(const uint4*)(qkvh + (nb + r) * 3072 + 1024 + hh * 64 + lch * 8);
    }
    __syncthreads();

    for (int kt = 0; kt < 8; kt++) {
#pragma unroll
        for (int i = 0; i < 2; i++)
            *(uint4*)(Kw + (lr + i * 32) * QKSTR + lch * 4) = kreg[i];
        __syncthreads();
        if (kt + 1 < 8) {
#pragma unroll
            for (int i = 0; i < 2; i++) {
                int r = lr + i * 32;
                kreg[i] = *(const uint4*)(qkvh + (nb + (kt + 1) * 64 + r) * 3072 +
                                          1024 + hh * 64 + lch * 8);
            }
        }
        float sc[2][2][4];
#pragma unroll
        for (int a = 0; a < 2; a++)
#pragma unroll
            for (int b = 0; b < 2; b++)
#pragma unroll
                for (int q = 0; q < 4; q++) sc[a][b][q] = 0.f;
#pragma unroll
        for (int ks = 0; ks < 4; ks++) {
            uint32_t af[2][4];
#pragma unroll
            for (int mt = 0; mt < 2; mt++) {
                const uint32_t* p = Qw + (wq * 32 + mt * 16 + g) * QKSTR + 8 * ks + t;
                af[mt][0] = p[0]; af[mt][1] = p[8 * QKSTR];
                af[mt][2] = p[4]; af[mt][3] = p[8 * QKSTR + 4];
            }
            uint32_t bf[2][2];
#pragma unroll
            for (int nt = 0; nt < 2; nt++) {
                const uint32_t* p = Kw + (wk * 16 + nt * 8 + g) * QKSTR + 8 * ks + t;
                bf[nt][0] = p[0]; bf[nt][1] = p[4];
            }
#pragma unroll
            for (int mt = 0; mt < 2; mt++)
#pragma unroll
                for (int nt = 0; nt < 2; nt++)
                    mma_f16(sc[mt][nt], af[mt], bf[nt]);
        }
#pragma unroll
        for (int mt = 0; mt < 2; mt++)
#pragma unroll
            for (int nt = 0; nt < 2; nt++) {
                int r = wq * 32 + mt * 16 + g;
                int c2 = kt * 32 + wk * 8 + nt * 4 + t;
                Sh2[r * SSTH2 + c2] =
                    __floats2half2_rn(sc[mt][nt][0] * 0.125f, sc[mt][nt][1] * 0.125f);
                Sh2[(r + 8) * SSTH2 + c2] =
                    __floats2half2_rn(sc[mt][nt][2] * 0.125f, sc[mt][nt][3] * 0.125f);
            }
        __syncthreads();
    }

    for (int r = wid; r < 64; r += 8) {
        __half2* row = Sh2 + r * SSTH2;
        float2 v[8];
        float mx = -1e30f;
#pragma unroll
        for (int c = 0; c < 8; c++) {
            v[c] = __half22float2(row[lane + 32 * c]);
            mx = fmaxf(mx, fmaxf(v[c].x, v[c].y));
        }
#pragma unroll
        for (int off = 16; off; off >>= 1)
            mx = fmaxf(mx, __shfl_xor_sync(0xffffffffu, mx, off));
        float sum = 0.f;
#pragma unroll
        for (int c = 0; c < 8; c++) {
            v[c].x = __expf(v[c].x - mx); v[c].y = __expf(v[c].y - mx);
            sum += v[c].x + v[c].y;
        }
#pragma unroll
        for (int off = 16; off; off >>= 1)
            sum += __shfl_xor_sync(0xffffffffu, sum, off);
        float inv = 1.f / sum;
#pragma unroll
        for (int c = 0; c < 8; c++)
            row[lane + 32 * c] = __floats2half2_rn(v[c].x * inv, v[c].y * inv);
    }
    __syncthreads();

    float oacc[2][2][4];
#pragma unroll
    for (int a = 0; a < 2; a++)
#pragma unroll
        for (int b = 0; b < 2; b++)
#pragma unroll
            for (int q = 0; q < 4; q++) oacc[a][b][q] = 0.f;

    const uint32_t* P32 = (const uint32_t*)smc;
    const int lm = lane >> 3, lrr = lane & 7;
    const uint32_t vrow_off = (uint32_t)(((lm & 1) * 8 + lrr) * 144 +
                                         (wk * 16 + (lm >> 1) * 8) * 2);
    const uint32_t vbase = sb + QOFF;

    uint4 vreg[2];
#pragma unroll
    for (int i = 0; i < 2; i++) {
        int node = lr + i * 32;
        vreg[i] = *(const uint4*)(qkvh + (nb + node) * 3072 + 2048 + hh * 64 + lch * 8);
    }

    for (int vt = 0; vt < 8; vt++) {
#pragma unroll
        for (int i = 0; i < 2; i++) {
            int node = lr + i * 32;
            *(uint4*)(Vh + node * 72 + lch * 8) = vreg[i];
        }
        __syncthreads();
        if (vt + 1 < 8) {
#pragma unroll
            for (int i = 0; i < 2; i++) {
                int node = lr + i * 32;
                vreg[i] = *(const uint4*)(qkvh + (nb + (vt + 1) * 64 + node) * 3072 +
                                          2048 + hh * 64 + lch * 8);
            }
        }
#pragma unroll
        for (int ks = 0; ks < 4; ks++) {
            uint32_t af[2][4];
#pragma unroll
            for (int mt = 0; mt < 2; mt++) {
                const uint32_t* p = P32 + (wq * 32 + mt * 16 + g) * SSTH2 +
                                    (vt * 64 + ks * 16) / 2 + t;
                af[mt][0] = p[0]; af[mt][1] = p[8 * SSTH2];
                af[mt][2] = p[4]; af[mt][3] = p[8 * SSTH2 + 4];
            }
            uint32_t b0, b1, b2, b3;
            ldsm4t(b0, b1, b2, b3, vbase + ks * 2304 + vrow_off);
            uint32_t bf[2][2] = {{b0, b1}, {b2, b3}};
#pragma unroll
            for (int mt = 0; mt < 2; mt++)
#pragma unroll
                for (int nt = 0; nt < 2; nt++)
                    mma_f16(oacc[mt][nt], af[mt], bf[nt]);
        }
        __syncthreads();
    }

#pragma unroll
    for (int mt = 0; mt < 2; mt++) {
        int r0 = wq * 32 + mt * 16 + g;
#pragma unroll
        for (int nt = 0; nt < 2; nt++) {
            int col = hh * 64 + wk * 16 + nt * 8 + 2 * t;
            size_t base = (nb + qt * 64 + r0) * 1024 + col;
            __half2 h0 = __floats2half2_rn(oacc[mt][nt][0], oacc[mt][nt][1]);
            __half2 h1 = __floats2half2_rn(oacc[mt][nt][2], oacc[mt][nt][3]);
            *(__half2*)(oh + base) = h0;
            *(__half2*)(oh + base + 8 * 1024) = h1;
        }
    }
}

// ---------------- fused residual add + LayerNorm (opt fp16 copy) ----------------
template <bool WH>
__global__ void __launch_bounds__(256) add_ln_kernel(
    const float* __restrict__ A, const float* __restrict__ B,
    const float* __restrict__ gamma, const float* __restrict__ beta,
    float* __restrict__ out, __half* __restrict__ outh)
{
    const int row = blockIdx.x;
    const int tid = threadIdx.x;
    const float4 a = ((const float4*)(A + (size_t)row * DIM))[tid];
    const float4 b = ((const float4*)(B + (size_t)row * DIM))[tid];
    float4 s = {a.x + b.x, a.y + b.y, a.z + b.z, a.w + b.w};
    float sum = s.x + s.y + s.z + s.w;
    float sq  = s.x * s.x + s.y * s.y + s.z * s.z + s.w * s.w;

    __shared__ float red[16];
#pragma unroll
    for (int off = 16; off; off >>= 1) {
        sum += __shfl_xor_sync(0xffffffffu, sum, off);
        sq  += __shfl_xor_sync(0xffffffffu, sq, off);
    }
    const int warp = tid >> 5, lane = tid & 31;
    if (lane == 0) { red[warp] = sum; red[8 + warp] = sq; }
    __syncthreads();
    sum = 0.f; sq = 0.f;
#pragma unroll
    for (int w = 0; w < 8; w++) { sum += red[w]; sq += red[8 + w]; }

    const float mean = sum * (1.0f / DIM);
    const float var  = sq * (1.0f / DIM) - mean * mean;
    const float inv  = rsqrtf(var + 1e-5f);
    const float4 gm = ((const float4*)gamma)[tid];
    const float4 be = ((const float4*)beta)[tid];
    float4 o;
    o.x = (s.x - mean) * inv * gm.x + be.x;
    o.y = (s.y - mean) * inv * gm.y + be.y;
    o.z = (s.z - mean) * inv * gm.z + be.z;
    o.w = (s.w - mean) * inv * gm.w + be.w;
    ((float4*)(out + (size_t)row * DIM))[tid] = o;
    if (WH) {
        __half2 h0 = __floats2half2_rn(o.x, o.y);
        __half2 h1 = __floats2half2_rn(o.z, o.w);
        uint2 u; u.x = *(uint32_t*)&h0; u.y = *(uint32_t*)&h1;
        ((uint2*)(outh + (size_t)row * DIM))[tid] = u;
    }
}

// ---------------- launcher ----------------
extern "C" void kernel_launch(void* const* d_in, const int* in_sizes, int n_in,
                              void* d_out, int out_size)
{
    const float* h     = (const float*)d_in[0];
    const float* w_in  = (const float*)d_in[1];
    const float* b_in  = (const float*)d_in[2];
    const float* w_out = (const float*)d_in[3];
    const float* b_out = (const float*)d_in[4];
    const float* ln1g  = (const float*)d_in[5];
    const float* ln1b  = (const float*)d_in[6];
    const float* ln2g  = (const float*)d_in[7];
    const float* ln2b  = (const float*)d_in[8];
    const float* fw1   = (const float*)d_in[9];
    const float* fb1   = (const float*)d_in[10];
    const float* fw2   = (const float*)d_in[11];
    const float* fb2   = (const float*)d_in[12];
    float* out = (float*)d_out;

    __half *h_h, *qkv_h, *attn_h, *x1_h, *f1_h, *win_h, *wout_h, *fw1_h, *fw2_h;
    float *tmp, *x1;
    cudaGetSymbolAddress((void**)&h_h,    g_h_h);
    cudaGetSymbolAddress((void**)&qkv_h,  g_qkv_h);
    cudaGetSymbolAddress((void**)&attn_h, g_attn_h);
    cudaGetSymbolAddress((void**)&x1_h,   g_x1_h);
    cudaGetSymbolAddress((void**)&f1_h,   g_f1_h);
    cudaGetSymbolAddress((void**)&win_h,  g_win_h);
    cudaGetSymbolAddress((void**)&wout_h, g_wout_h);
    cudaGetSymbolAddress((void**)&fw1_h,  g_fw1_h);
    cudaGetSymbolAddress((void**)&fw2_h,  g_fw2_h);
    cudaGetSymbolAddress((void**)&tmp,    g_tmp);
    cudaGetSymbolAddress((void**)&x1,     g_x1);

    cudaFuncSetAttribute(gemm_h<false, true>,
                         cudaFuncAttributeMaxDynamicSharedMemorySize, GEMM_SMEM);
    cudaFuncSetAttribute(gemm_h<false, false>,
                         cudaFuncAttributeMaxDynamicSharedMemorySize, GEMM_SMEM);
    cudaFuncSetAttribute(gemm_h<true, true>,
                         cudaFuncAttributeMaxDynamicSharedMemorySize, GEMM_SMEM);
    cudaFuncSetAttribute(attn_mma,
                         cudaFuncAttributeMaxDynamicSharedMemorySize, ATTN_SMEM);

    // 0) fp16 conversions (single launch)
    f32_to_f16_all<<<(CNT + 255) / 256, 256>>>(
        h, h_h, w_in, win_h, w_out, wout_h, fw1, fw1_h, fw2, fw2_h);

    // 1) QKV
    gemm_h<false, true><<<dim3(3 * DIM / BN, T_NODES / BM), 256, GEMM_SMEM>>>(
        h_h, win_h, b_in, nullptr, qkv_h, T_NODES, 3 * DIM, DIM);
    // 2) attention
    attn_mma<<<dim3(8, NHEAD, NGRAPH), 256, ATTN_SMEM>>>(qkv_h, attn_h);
    // 3) out-proj
    gemm_h<false, false><<<dim3(DIM / BN, T_NODES / BM), 256, GEMM_SMEM>>>(
        attn_h, wout_h, b_out, tmp, nullptr, T_NODES, DIM, DIM);
    // 4) LN1
    add_ln_kernel<true><<<T_NODES, 256>>>(h, tmp, ln1g, ln1b, x1, x1_h);
    // 5) FFN1 + ReLU
    gemm_h<true, true><<<dim3(2 * DIM / BN, T_NODES / BM), 256, GEMM_SMEM>>>(
        x1_h, fw1_h, fb1, nullptr, f1_h, T_NODES, 2 * DIM, DIM);
    // 6) FFN2
    gemm_h<false, false><<<dim3(DIM / BN, T_NODES / BM), 256, GEMM_SMEM>>>(
        f1_h, fw2_h, fb2, tmp, nullptr, T_NODES, DIM, 2 * DIM);
    // 7) LN2
    add_ln_kernel<false><<<T_NODES, 256>>>(x1, tmp, ln2g, ln2b, out, nullptr);
}

// round 14
// speedup vs baseline: 1.0384x; 1.0384x over previous
#include <cuda_runtime.h>
#include <cuda_fp16.h>
#include <cstdint>
#include <math.h>

#define T_NODES 16384
#define DIM     1024
#define NHEAD   16
#define HD      64
#define NGRAPH  32
#define NPG     512

// ---------------- scratch (device globals) ----------------
__device__ __half g_h_h  [(size_t)T_NODES * DIM];
__device__ __half g_qkv_h[(size_t)T_NODES * 3 * DIM];
__device__ __half g_attn_h[(size_t)T_NODES * DIM];
__device__ __half g_x1_h [(size_t)T_NODES * DIM];
__device__ __half g_f1_h [(size_t)T_NODES * 2 * DIM];
__device__ __half g_win_h [3 * DIM * DIM];
__device__ __half g_wout_h[DIM * DIM];
__device__ __half g_fw1_h [2 * DIM * DIM];
__device__ __half g_fw2_h [2 * DIM * DIM];
__device__ float  g_tmp[(size_t)T_NODES * DIM];
__device__ float  g_x1 [(size_t)T_NODES * DIM];

// ---------------- helpers ----------------
__device__ __forceinline__ uint32_t smem_u32(const void* p) {
    uint32_t a;
    asm("{ .reg .u64 t; cvta.to.shared.u64 t, %1; cvt.u32.u64 %0, t; }" : "=r"(a) : "l"(p));
    return a;
}
__device__ __forceinline__ void mma_f16(float* c, const uint32_t* a, const uint32_t* b) {
    asm volatile(
        "mma.sync.aligned.m16n8k16.row.col.f32.f16.f16.f32 "
        "{%0,%1,%2,%3}, {%4,%5,%6,%7}, {%8,%9}, {%0,%1,%2,%3};"
        : "+f"(c[0]), "+f"(c[1]), "+f"(c[2]), "+f"(c[3])
        : "r"(a[0]), "r"(a[1]), "r"(a[2]), "r"(a[3]), "r"(b[0]), "r"(b[1]));
}
__device__ __forceinline__ void ldsm4(uint32_t& r0, uint32_t& r1, uint32_t& r2,
                                      uint32_t& r3, uint32_t addr) {
    asm volatile("ldmatrix.sync.aligned.m8n8.x4.shared.b16 {%0,%1,%2,%3}, [%4];"
                 : "=r"(r0), "=r"(r1), "=r"(r2), "=r"(r3) : "r"(addr));
}
__device__ __forceinline__ void ldsm4t(uint32_t& r0, uint32_t& r1, uint32_t& r2,
                                       uint32_t& r3, uint32_t addr) {
    asm volatile("ldmatrix.sync.aligned.m8n8.x4.trans.shared.b16 {%0,%1,%2,%3}, [%4];"
                 : "=r"(r0), "=r"(r1), "=r"(r2), "=r"(r3) : "r"(addr));
}
__device__ __forceinline__ uint32_t lds32(uint32_t addr) {
    uint32_t v;
    asm volatile("ld.shared.b32 %0, [%1];" : "=r"(v) : "r"(addr));
    return v;
}
__device__ __forceinline__ void cp16(uint32_t dst, const void* src) {
    asm volatile("cp.async.cg.shared.global [%0], [%1], 16;" :: "r"(dst), "l"(src));
}
__device__ __forceinline__ void cp_commit() { asm volatile("cp.async.commit_group;"); }
template <int N>
__device__ __forceinline__ void cp_wait() {
    asm volatile("cp.async.wait_group %0;" :: "n"(N));
}

// ---------------- fused fp32 -> fp16 converts (one launch) ----------------
#define CN0 (T_NODES * DIM / 4)
#define CN1 (3 * DIM * DIM / 4)
#define CN2 (DIM * DIM / 4)
#define CN3 (2 * DIM * DIM / 4)
#define CN4 (2 * DIM * DIM / 4)
#define CNT (CN0 + CN1 + CN2 + CN3 + CN4)

__global__ void __launch_bounds__(256) f32_to_f16_all(
    const float* __restrict__ a0, __half* __restrict__ b0,
    const float* __restrict__ a1, __half* __restrict__ b1,
    const float* __restrict__ a2, __half* __restrict__ b2,
    const float* __restrict__ a3, __half* __restrict__ b3,
    const float* __restrict__ a4, __half* __restrict__ b4)
{
    int i = blockIdx.x * 256 + threadIdx.x;
    if (i >= CNT) return;
    const float* s; __half* d; int off;
    if (i < CN0)                       { s = a0; d = b0; off = i; }
    else if (i < CN0 + CN1)            { s = a1; d = b1; off = i - CN0; }
    else if (i < CN0 + CN1 + CN2)      { s = a2; d = b2; off = i - CN0 - CN1; }
    else if (i < CN0 + CN1 + CN2 + CN3){ s = a3; d = b3; off = i - CN0 - CN1 - CN2; }
    else                               { s = a4; d = b4; off = i - CN0 - CN1 - CN2 - CN3; }
    float4 v = ((const float4*)s)[off];
    __half2 x = __floats2half2_rn(v.x, v.y);
    __half2 y = __floats2half2_rn(v.z, v.w);
    uint2 u; u.x = *(uint32_t*)&x; u.y = *(uint32_t*)&y;
    ((uint2*)d)[off] = u;
}

// ============================ fp16 mma GEMM (R11 best + fused residual) ==========
#define BM 128
#define BN 128
#define BKH 64
#define A_BYTES (BM * 128)
#define B_BYTES (BN * 128)
#define SLOT_BYTES (A_BYTES + B_BYTES)          // 32768
#define NSLOT 3
#define GEMM_SMEM (NSLOT * SLOT_BYTES + 512)    // 98816 -> 2 CTAs/SM

template <bool RELU, bool OUTH, bool ADDRES>
__global__ void __launch_bounds__(256, 2) gemm_h(
    const __half* __restrict__ A, const __half* __restrict__ B,
    const float* __restrict__ bias, float* __restrict__ Cf,
    __half* __restrict__ Ch, const float* __restrict__ Rres,
    int M, int N, int K)
{
    extern __shared__ char smem[];
    const uint32_t sbase = smem_u32(smem);
    float* sbias = (float*)(smem + NSLOT * SLOT_BYTES);

    const int tid = threadIdx.x;
    const int wid = tid >> 5, lane = tid & 31;
    const int g = lane >> 2, t = lane & 3;
    const int wm = wid & 1, wn = wid >> 1;
    const int m0 = blockIdx.y * BM, n0 = blockIdx.x * BN;

    if (tid < BN) sbias[tid] = bias[n0 + tid];

    const int lrow = lane & 15;
    const int lsel = lane >> 4;
    const int lxor = lane & 7;
    uint32_t aoff[4], boff[2];
#pragma unroll
    for (int mt = 0; mt < 4; mt++)
        aoff[mt] = (wm * 64 + mt * 16 + lrow) * 128;
#pragma unroll
    for (int pr = 0; pr < 2; pr++)
        boff[pr] = A_BYTES + (wn * 32 + pr * 16 + lrow) * 128;

    float acc[4][4][4];
#pragma unroll
    for (int i = 0; i < 4; i++)
#pragma unroll
        for (int j = 0; j < 4; j++)
#pragma unroll
            for (int q = 0; q < 4; q++) acc[i][j][q] = 0.f;

    const int NC = K / BKH;

    auto loadc = [&](int c, int slot) {
        const uint32_t sA = sbase + slot * SLOT_BYTES;
        const uint32_t sB = sA + A_BYTES;
        const __half* Ab = A + (size_t)m0 * K + c * BKH;
        const __half* Bb = B + (size_t)n0 * K + c * BKH;
#pragma unroll
        for (int i = 0; i < 4; i++) {
            int idx = tid + i * 256;
            int r = idx >> 3, ch = idx & 7;
            cp16(sA + r * 128 + ((ch ^ (r & 7)) << 4), Ab + (size_t)r * K + ch * 8);
        }
#pragma unroll
        for (int i = 0; i < 4; i++) {
            int idx = tid + i * 256;
            int r = idx >> 3, ch = idx & 7;
            cp16(sB + r * 128 + ((ch ^ (r & 7)) << 4), Bb + (size_t)r * K + ch * 8);
        }
    };

    loadc(0, 0); cp_commit();
    loadc(1, 1); cp_commit();

    int slot = 0;
    for (int c = 0; c < NC; c++) {
        if (c + 2 < NC) cp_wait<1>(); else cp_wait<0>();
        __syncthreads();
        int nslot = slot + 2; if (nslot >= NSLOT) nslot -= NSLOT;
        if (c + 2 < NC) { loadc(c + 2, nslot); cp_commit(); }

        const uint32_t slotb = sbase + slot * SLOT_BYTES;
#pragma unroll
        for (int ks = 0; ks < 4; ks++) {
            const uint32_t cb = (uint32_t)(((2 * ks + lsel) ^ lxor) << 4);
            uint32_t af[4][4];
#pragma unroll
            for (int mt = 0; mt < 4; mt++)
                ldsm4(af[mt][0], af[mt][1], af[mt][2], af[mt][3],
                      slotb + aoff[mt] + cb);
            uint32_t bf[4][2];
#pragma unroll
            for (int pr = 0; pr < 2; pr++) {
                uint32_t r0, r1, r2, r3;
                ldsm4(r0, r1, r2, r3, slotb + boff[pr] + cb);
                bf[2 * pr][0] = r0; bf[2 * pr][1] = r2;
                bf[2 * pr + 1][0] = r1; bf[2 * pr + 1][1] = r3;
            }
#pragma unroll
            for (int mt = 0; mt < 4; mt++)
#pragma unroll
                for (int nt = 0; nt < 4; nt++)
                    mma_f16(acc[mt][nt], af[mt], bf[nt]);
        }
        if (++slot >= NSLOT) slot = 0;
    }

    // epilogue
#pragma unroll
    for (int mt = 0; mt < 4; mt++) {
        const int row = m0 + wm * 64 + mt * 16 + g;
#pragma unroll
        for (int nt = 0; nt < 4; nt++) {
            const int cc = wn * 32 + nt * 8 + 2 * t;
            float b0 = sbias[cc], b1 = sbias[cc + 1];
            float r00 = acc[mt][nt][0] + b0, r01 = acc[mt][nt][1] + b1;
            float r10 = acc[mt][nt][2] + b0, r11 = acc[mt][nt][3] + b1;
            if (ADDRES) {
                float2 q0 = *(const float2*)(Rres + (size_t)row * N + n0 + cc);
                float2 q1 = *(const float2*)(Rres + (size_t)(row + 8) * N + n0 + cc);
                r00 += q0.x; r01 += q0.y; r10 += q1.x; r11 += q1.y;
            }
            if (RELU) {
                r00 = fmaxf(r00, 0.f); r01 = fmaxf(r01, 0.f);
                r10 = fmaxf(r10, 0.f); r11 = fmaxf(r11, 0.f);
            }
            if (OUTH) {
                __half2 h0 = __floats2half2_rn(r00, r01);
                __half2 h1 = __floats2half2_rn(r10, r11);
                *(__half2*)(Ch + (size_t)row * N + n0 + cc) = h0;
                *(__half2*)(Ch + (size_t)(row + 8) * N + n0 + cc) = h1;
            } else {
                float2 v0 = {r00, r01}, v1 = {r10, r11};
                *(float2*)(Cf + (size_t)row * N + n0 + cc) = v0;
                *(float2*)(Cf + (size_t)(row + 8) * N + n0 + cc) = v1;
            }
        }
    }
}

// ============================ attention v3 (tail-wait fixed) ============================
#define SSTH2 260
#define S_BYTES (64 * SSTH2 * 4)           // 66560
#define QOFF S_BYTES                       // Q tile 8KB; reused as V buf 0
#define KOFF0 (QOFF + 8192)                // K bufs 0..2
#define ATTN_SMEM (KOFF0 + 3 * 8192)       // 99328 -> 2 CTAs/SM

__global__ void __launch_bounds__(256, 2) attn_mma(
    const __half* __restrict__ qkvh, __half* __restrict__ oh)
{
    extern __shared__ char smc[];
    __half2* Sh2 = (__half2*)smc;
    const uint32_t sb = smem_u32(smc);

    const int tid = threadIdx.x;
    const int wid = tid >> 5, lane = tid & 31;
    const int g = lane >> 2, t = lane & 3;
    const int wq = wid & 1, wk = wid >> 1;
    const int qt = blockIdx.x, hh = blockIdx.y, gg = blockIdx.z;
    const size_t nb = (size_t)gg * NPG;

    const int lr = tid >> 3, lch = tid & 7;

    // issue Q tile, K tiles 0,1 (one group each)
#pragma unroll
    for (int i = 0; i < 2; i++) {
        int r = lr + i * 32;
        cp16(sb + QOFF + r * 128 + (((uint32_t)lch ^ (r & 7)) << 4),
             qkvh + (nb + qt * 64 + r) * 3072 + hh * 64 + lch * 8);
    }
    cp_commit();
#pragma unroll
    for (int j = 0; j < 2; j++) {
#pragma unroll
        for (int i = 0; i < 2; i++) {
            int r = lr + i * 32;
            cp16(sb + KOFF0 + j * 8192 + r * 128 + (((uint32_t)lch ^ (r & 7)) << 4),
                 qkvh + (nb + j * 64 + r) * 3072 + 1024 + hh * 64 + lch * 8);
        }
        cp_commit();
    }

    cp_wait<1>();          // Q + K0 complete
    __syncthreads();

    // hoist stationary Q fragments
    uint32_t afq[4][2][4];
#pragma unroll
    for (int ks = 0; ks < 4; ks++)
#pragma unroll
        for (int mt = 0; mt < 2; mt++) {
            uint32_t qb = sb + QOFF + (wq * 32 + mt * 16 + g) * 128 + (t << 2);
            uint32_t c0 = (uint32_t)(((2 * ks) ^ g) << 4);
            uint32_t c1 = (uint32_t)(((2 * ks + 1) ^ g) << 4);
            afq[ks][mt][0] = lds32(qb + c0);
            afq[ks][mt][1] = lds32(qb + 8 * 128 + c0);
            afq[ks][mt][2] = lds32(qb + c1);
            afq[ks][mt][3] = lds32(qb + 8 * 128 + c1);
        }

    // ---- QK^T ----
    for (int kt = 0; kt < 8; kt++) {
        if (kt) {
            if (kt + 2 < 8) cp_wait<1>(); else cp_wait<0>();
            __syncthreads();
        }
        if (kt + 2 < 8) {
            int j = (kt + 2) % 3;
#pragma unroll
            for (int i = 0; i < 2; i++) {
                int r = lr + i * 32;
                cp16(sb + KOFF0 + j * 8192 + r * 128 + (((uint32_t)lch ^ (r & 7)) << 4),
                     qkvh + (nb + (kt + 2) * 64 + r) * 3072 + 1024 + hh * 64 + lch * 8);
            }
            cp_commit();
        }
        const uint32_t kb = sb + KOFF0 + (kt % 3) * 8192;

        float sc[2][2][4];
#pragma unroll
        for (int a = 0; a < 2; a++)
#pragma unroll
            for (int b = 0; b < 2; b++)
#pragma unroll
                for (int q = 0; q < 4; q++) sc[a][b][q] = 0.f;
#pragma unroll
        for (int ks = 0; ks < 4; ks++) {
            uint32_t bf[2][2];
#pragma unroll
            for (int nt = 0; nt < 2; nt++) {
                uint32_t base = kb + (wk * 16 + nt * 8 + g) * 128 + (t << 2);
                bf[nt][0] = lds32(base + (uint32_t)(((2 * ks) ^ g) << 4));
                bf[nt][1] = lds32(base + (uint32_t)(((2 * ks + 1) ^ g) << 4));
            }
#pragma unroll
            for (int mt = 0; mt < 2; mt++)
#pragma unroll
                for (int nt = 0; nt < 2; nt++)
                    mma_f16(sc[mt][nt], afq[ks][mt], bf[nt]);
        }
#pragma unroll
        for (int mt = 0; mt < 2; mt++)
#pragma unroll
            for (int nt = 0; nt < 2; nt++) {
                int r = wq * 32 + mt * 16 + g;
                int c2 = kt * 32 + wk * 8 + nt * 4 + t;
                Sh2[r * SSTH2 + c2] =
                    __floats2half2_rn(sc[mt][nt][0] * 0.125f, sc[mt][nt][1] * 0.125f);
                Sh2[(r + 8) * SSTH2 + c2] =
                    __floats2half2_rn(sc[mt][nt][2] * 0.125f, sc[mt][nt][3] * 0.125f);
            }
    }
    __syncthreads();   // S complete; all K/Q reads done

    // issue V tiles 0,1 (overlay Q / K0 regions)
#pragma unroll
    for (int j = 0; j < 2; j++) {
#pragma unroll
        for (int i = 0; i < 2; i++) {
            int r = lr + i * 32;
            cp16(sb + QOFF + j * 8192 + r * 128 + (((uint32_t)lch ^ (r & 7)) << 4),
                 qkvh + (nb + j * 64 + r) * 3072 + 2048 + hh * 64 + lch * 8);
        }
        cp_commit();
    }

    // ---- softmax (normalized P written back fp16) ----
    for (int r = wid; r < 64; r += 8) {
        __half2* row = Sh2 + r * SSTH2;
        float2 v[8];
        float mx = -1e30f;
#pragma unroll
        for (int c = 0; c < 8; c++) {
            v[c] = __half22float2(row[lane + 32 * c]);
            mx = fmaxf(mx, fmaxf(v[c].x, v[c].y));
        }
#pragma unroll
        for (int off = 16; off; off >>= 1)
            mx = fmaxf(mx, __shfl_xor_sync(0xffffffffu, mx, off));
        float sum = 0.f;
#pragma unroll
        for (int c = 0; c < 8; c++) {
            v[c].x = __expf(v[c].x - mx); v[c].y = __expf(v[c].y - mx);
            sum += v[c].x + v[c].y;
        }
#pragma unroll
        for (int off = 16; off; off >>= 1)
            sum += __shfl_xor_sync(0xffffffffu, sum, off);
        float inv = 1.f / sum;
#pragma unroll
        for (int c = 0; c < 8; c++)
            row[lane + 32 * c] = __floats2half2_rn(v[c].x * inv, v[c].y * inv);
    }
    __syncthreads();

    // ---- P @ V ----
    float oacc[2][2][4];
#pragma unroll
    for (int a = 0; a < 2; a++)
#pragma unroll
        for (int b = 0; b < 2; b++)
#pragma unroll
            for (int q = 0; q < 4; q++) oacc[a][b][q] = 0.f;

    const uint32_t* P32 = (const uint32_t*)smc;
    const int lm = lane >> 3, lrr = lane & 7;
    const uint32_t vchunk = (uint32_t)(2 * wk + (lm >> 1));
    const uint32_t vnodeb = (uint32_t)((lm & 1) * 8 + lrr);

    for (int vt = 0; vt < 8; vt++) {
        if (vt + 2 < 8) cp_wait<1>(); else cp_wait<0>();
        __syncthreads();
        if (vt + 2 < 8) {
            int j = (vt + 2) % 3;
#pragma unroll
            for (int i = 0; i < 2; i++) {
                int r = lr + i * 32;
                cp16(sb + QOFF + j * 8192 + r * 128 + (((uint32_t)lch ^ (r & 7)) << 4),
                     qkvh + (nb + (vt + 2) * 64 + r) * 3072 + 2048 + hh * 64 + lch * 8);
            }
            cp_commit();
        }
        const uint32_t vb = sb + QOFF + (vt % 3) * 8192;
#pragma unroll
        for (int ks = 0; ks < 4; ks++) {
            uint32_t af[2][4];
#pragma unroll
            for (int mt = 0; mt < 2; mt++) {
                const uint32_t* p = P32 + (wq * 32 + mt * 16 + g) * SSTH2 +
                                    vt * 32 + ks * 8 + t;
                af[mt][0] = p[0]; af[mt][1] = p[8 * SSTH2];
                af[mt][2] = p[4]; af[mt][3] = p[8 * SSTH2 + 4];
            }
            uint32_t nl = (uint32_t)(ks * 16) + vnodeb;
            uint32_t b0, b1, b2, b3;
            ldsm4t(b0, b1, b2, b3, vb + nl * 128 + ((vchunk ^ lrr) << 4));
            uint32_t bf[2][2] = {{b0, b1}, {b2, b3}};
#pragma unroll
            for (int mt = 0; mt < 2; mt++)
#pragma unroll
                for (int nt = 0; nt < 2; nt++)
                    mma_f16(oacc[mt][nt], af[mt], bf[nt]);
        }
    }

    // ---- epilogue ----
#pragma unroll
    for (int mt = 0; mt < 2; mt++) {
        int r0 = wq * 32 + mt * 16 + g;
#pragma unroll
        for (int nt = 0; nt < 2; nt++) {
            int col = hh * 64 + wk * 16 + nt * 8 + 2 * t;
            size_t base = (nb + qt * 64 + r0) * 1024 + col;
            __half2 h0 = __floats2half2_rn(oacc[mt][nt][0], oacc[mt][nt][1]);
            __half2 h1 = __floats2half2_rn(oacc[mt][nt][2], oacc[mt][nt][3]);
            *(__half2*)(oh + base) = h0;
            *(__half2*)(oh + base + 8 * 1024) = h1;
        }
    }
}

// ---------------- LayerNorm (single input; residual pre-fused in GEMM) ------------
template <bool WH>
__global__ void __launch_bounds__(256) ln_kernel(
    const float* __restrict__ X,
    const float* __restrict__ gamma, const float* __restrict__ beta,
    float* __restrict__ out, __half* __restrict__ outh)
{
    const int row = blockIdx.x;
    const int tid = threadIdx.x;
    const float4 s = ((const float4*)(X + (size_t)row * DIM))[tid];
    float sum = s.x + s.y + s.z + s.w;
    float sq  = s.x * s.x + s.y * s.y + s.z * s.z + s.w * s.w;

    __shared__ float red[16];
#pragma unroll
    for (int off = 16; off; off >>= 1) {
        sum += __shfl_xor_sync(0xffffffffu, sum, off);
        sq  += __shfl_xor_sync(0xffffffffu, sq, off);
    }
    const int warp = tid >> 5, lane = tid & 31;
    if (lane == 0) { red[warp] = sum; red[8 + warp] = sq; }
    __syncthreads();
    sum = 0.f; sq = 0.f;
#pragma unroll
    for (int w = 0; w < 8; w++) { sum += red[w]; sq += red[8 + w]; }

    const float mean = sum * (1.0f / DIM);
    const float var  = sq * (1.0f / DIM) - mean * mean;
    const float inv  = rsqrtf(var + 1e-5f);
    const float4 gm = ((const float4*)gamma)[tid];
    const float4 be = ((const float4*)beta)[tid];
    float4 o;
    o.x = (s.x - mean) * inv * gm.x + be.x;
    o.y = (s.y - mean) * inv * gm.y + be.y;
    o.z = (s.z - mean) * inv * gm.z + be.z;
    o.w = (s.w - mean) * inv * gm.w + be.w;
    ((float4*)(out + (size_t)row * DIM))[tid] = o;
    if (WH) {
        __half2 h0 = __floats2half2_rn(o.x, o.y);
        __half2 h1 = __floats2half2_rn(o.z, o.w);
        uint2 u; u.x = *(uint32_t*)&h0; u.y = *(uint32_t*)&h1;
        ((uint2*)(outh + (size_t)row * DIM))[tid] = u;
    }
}

// ---------------- launcher ----------------
extern "C" void kernel_launch(void* const* d_in, const int* in_sizes, int n_in,
                              void* d_out, int out_size)
{
    const float* h     = (const float*)d_in[0];
    const float* w_in  = (const float*)d_in[1];
    const float* b_in  = (const float*)d_in[2];
    const float* w_out = (const float*)d_in[3];
    const float* b_out = (const float*)d_in[4];
    const float* ln1g  = (const float*)d_in[5];
    const float* ln1b  = (const float*)d_in[6];
    const float* ln2g  = (const float*)d_in[7];
    const float* ln2b  = (const float*)d_in[8];
    const float* fw1   = (const float*)d_in[9];
    const float* fb1   = (const float*)d_in[10];
    const float* fw2   = (const float*)d_in[11];
    const float* fb2   = (const float*)d_in[12];
    float* out = (float*)d_out;

    __half *h_h, *qkv_h, *attn_h, *x1_h, *f1_h, *win_h, *wout_h, *fw1_h, *fw2_h;
    float *tmp, *x1;
    cudaGetSymbolAddress((void**)&h_h,    g_h_h);
    cudaGetSymbolAddress((void**)&qkv_h,  g_qkv_h);
    cudaGetSymbolAddress((void**)&attn_h, g_attn_h);
    cudaGetSymbolAddress((void**)&x1_h,   g_x1_h);
    cudaGetSymbolAddress((void**)&f1_h,   g_f1_h);
    cudaGetSymbolAddress((void**)&win_h,  g_win_h);
    cudaGetSymbolAddress((void**)&wout_h, g_wout_h);
    cudaGetSymbolAddress((void**)&fw1_h,  g_fw1_h);
    cudaGetSymbolAddress((void**)&fw2_h,  g_fw2_h);
    cudaGetSymbolAddress((void**)&tmp,    g_tmp);
    cudaGetSymbolAddress((void**)&x1,     g_x1);

    cudaFuncSetAttribute(gemm_h<false, true, false>,
                         cudaFuncAttributeMaxDynamicSharedMemorySize, GEMM_SMEM);
    cudaFuncSetAttribute(gemm_h<false, false, true>,
                         cudaFuncAttributeMaxDynamicSharedMemorySize, GEMM_SMEM);
    cudaFuncSetAttribute(gemm_h<true, true, false>,
                         cudaFuncAttributeMaxDynamicSharedMemorySize, GEMM_SMEM);
    cudaFuncSetAttribute(attn_mma,
                         cudaFuncAttributeMaxDynamicSharedMemorySize, ATTN_SMEM);

    // 0) fp16 conversions (single launch)
    f32_to_f16_all<<<(CNT + 255) / 256, 256>>>(
        h, h_h, w_in, win_h, w_out, wout_h, fw1, fw1_h, fw2, fw2_h);

    // 1) QKV
    gemm_h<false, true, false><<<dim3(3 * DIM / BN, T_NODES / BM), 256, GEMM_SMEM>>>(
        h_h, win_h, b_in, nullptr, qkv_h, nullptr, T_NODES, 3 * DIM, DIM);
    // 2) attention
    attn_mma<<<dim3(8, NHEAD, NGRAPH), 256, ATTN_SMEM>>>(qkv_h, attn_h);
    // 3) out-proj + residual(h) -> tmp
    gemm_h<false, false, true><<<dim3(DIM / BN, T_NODES / BM), 256, GEMM_SMEM>>>(
        attn_h, wout_h, b_out, tmp, nullptr, h, T_NODES, DIM, DIM);
    // 4) x1 = LN1(tmp)
    ln_kernel<true><<<T_NODES, 256>>>(tmp, ln1g, ln1b, x1, x1_h);
    // 5) FFN1 + ReLU
    gemm_h<true, true, false><<<dim3(2 * DIM / BN, T_NODES / BM), 256, GEMM_SMEM>>>(
        x1_h, fw1_h, fb1, nullptr, f1_h, nullptr, T_NODES, 2 * DIM, DIM);
    // 6) FFN2 + residual(x1) -> tmp
    gemm_h<false, false, true><<<dim3(DIM / BN, T_NODES / BM), 256, GEMM_SMEM>>>(
        f1_h, fw2_h, fb2, tmp, nullptr, x1, T_NODES, DIM, 2 * DIM);
    // 7) out = LN2(tmp)
    ln_kernel<false><<<T_NODES, 256>>>(tmp, ln2g, ln2b, out, nullptr);
}

// round 15
// speedup vs baseline: 1.0564x; 1.0173x over previous
#include <cuda_runtime.h>
#include <cuda_fp16.h>
#include <cstdint>
#include <math.h>

#define T_NODES 16384
#define DIM     1024
#define NHEAD   16
#define HD      64
#define NGRAPH  32
#define NPG     512

// ---------------- scratch (device globals) ----------------
__device__ __half g_h_h  [(size_t)T_NODES * DIM];
__device__ __half g_qkv_h[(size_t)T_NODES * 3 * DIM];
__device__ __half g_attn_h[(size_t)T_NODES * DIM];
__device__ __half g_x1_h [(size_t)T_NODES * DIM];
__device__ __half g_tmp_h[(size_t)T_NODES * DIM];
__device__ __half g_f1_h [(size_t)T_NODES * 2 * DIM];
__device__ __half g_win_h [3 * DIM * DIM];
__device__ __half g_wout_h[DIM * DIM];
__device__ __half g_fw1_h [2 * DIM * DIM];
__device__ __half g_fw2_h [2 * DIM * DIM];

// ---------------- helpers ----------------
__device__ __forceinline__ uint32_t smem_u32(const void* p) {
    uint32_t a;
    asm("{ .reg .u64 t; cvta.to.shared.u64 t, %1; cvt.u32.u64 %0, t; }" : "=r"(a) : "l"(p));
    return a;
}
__device__ __forceinline__ void mma_f16(float* c, const uint32_t* a, const uint32_t* b) {
    asm volatile(
        "mma.sync.aligned.m16n8k16.row.col.f32.f16.f16.f32 "
        "{%0,%1,%2,%3}, {%4,%5,%6,%7}, {%8,%9}, {%0,%1,%2,%3};"
        : "+f"(c[0]), "+f"(c[1]), "+f"(c[2]), "+f"(c[3])
        : "r"(a[0]), "r"(a[1]), "r"(a[2]), "r"(a[3]), "r"(b[0]), "r"(b[1]));
}
__device__ __forceinline__ void ldsm4(uint32_t& r0, uint32_t& r1, uint32_t& r2,
                                      uint32_t& r3, uint32_t addr) {
    asm volatile("ldmatrix.sync.aligned.m8n8.x4.shared.b16 {%0,%1,%2,%3}, [%4];"
                 : "=r"(r0), "=r"(r1), "=r"(r2), "=r"(r3) : "r"(addr));
}
__device__ __forceinline__ void ldsm4t(uint32_t& r0, uint32_t& r1, uint32_t& r2,
                                       uint32_t& r3, uint32_t addr) {
    asm volatile("ldmatrix.sync.aligned.m8n8.x4.trans.shared.b16 {%0,%1,%2,%3}, [%4];"
                 : "=r"(r0), "=r"(r1), "=r"(r2), "=r"(r3) : "r"(addr));
}
__device__ __forceinline__ uint32_t lds32(uint32_t addr) {
    uint32_t v;
    asm volatile("ld.shared.b32 %0, [%1];" : "=r"(v) : "r"(addr));
    return v;
}
__device__ __forceinline__ void cp16(uint32_t dst, const void* src) {
    asm volatile("cp.async.cg.shared.global [%0], [%1], 16;" :: "r"(dst), "l"(src));
}
__device__ __forceinline__ void cp_commit() { asm volatile("cp.async.commit_group;"); }
template <int N>
__device__ __forceinline__ void cp_wait() {
    asm volatile("cp.async.wait_group %0;" :: "n"(N));
}

// ---------------- fused fp32 -> fp16 converts (one launch) ----------------
#define CN0 (T_NODES * DIM / 4)
#define CN1 (3 * DIM * DIM / 4)
#define CN2 (DIM * DIM / 4)
#define CN3 (2 * DIM * DIM / 4)
#define CN4 (2 * DIM * DIM / 4)
#define CNT (CN0 + CN1 + CN2 + CN3 + CN4)

__global__ void __launch_bounds__(256) f32_to_f16_all(
    const float* __restrict__ a0, __half* __restrict__ b0,
    const float* __restrict__ a1, __half* __restrict__ b1,
    const float* __restrict__ a2, __half* __restrict__ b2,
    const float* __restrict__ a3, __half* __restrict__ b3,
    const float* __restrict__ a4, __half* __restrict__ b4)
{
    int i = blockIdx.x * 256 + threadIdx.x;
    if (i >= CNT) return;
    const float* s; __half* d; int off;
    if (i < CN0)                       { s = a0; d = b0; off = i; }
    else if (i < CN0 + CN1)            { s = a1; d = b1; off = i - CN0; }
    else if (i < CN0 + CN1 + CN2)      { s = a2; d = b2; off = i - CN0 - CN1; }
    else if (i < CN0 + CN1 + CN2 + CN3){ s = a3; d = b3; off = i - CN0 - CN1 - CN2; }
    else                               { s = a4; d = b4; off = i - CN0 - CN1 - CN2 - CN3; }
    float4 v = ((const float4*)s)[off];
    __half2 x = __floats2half2_rn(v.x, v.y);
    __half2 y = __floats2half2_rn(v.z, v.w);
    uint2 u; u.x = *(uint32_t*)&x; u.y = *(uint32_t*)&y;
    ((uint2*)d)[off] = u;
}

// ============================ fp16 mma GEMM (fp16 residual + fp16 out) ==========
#define BM 128
#define BN 128
#define BKH 64
#define A_BYTES (BM * 128)
#define B_BYTES (BN * 128)
#define SLOT_BYTES (A_BYTES + B_BYTES)          // 32768
#define NSLOT 3
#define GEMM_SMEM (NSLOT * SLOT_BYTES + 512)    // 98816 -> 2 CTAs/SM

template <bool RELU, bool ADDRES>
__global__ void __launch_bounds__(256, 2) gemm_h(
    const __half* __restrict__ A, const __half* __restrict__ B,
    const float* __restrict__ bias, __half* __restrict__ Ch,
    const __half* __restrict__ RresH, int M, int N, int K)
{
    extern __shared__ char smem[];
    const uint32_t sbase = smem_u32(smem);
    float* sbias = (float*)(smem + NSLOT * SLOT_BYTES);

    const int tid = threadIdx.x;
    const int wid = tid >> 5, lane = tid & 31;
    const int g = lane >> 2, t = lane & 3;
    const int wm = wid & 1, wn = wid >> 1;
    const int m0 = blockIdx.y * BM, n0 = blockIdx.x * BN;

    if (tid < BN) sbias[tid] = bias[n0 + tid];

    const int lrow = lane & 15;
    const int lsel = lane >> 4;
    const int lxor = lane & 7;
    uint32_t aoff[4], boff[2];
#pragma unroll
    for (int mt = 0; mt < 4; mt++)
        aoff[mt] = (wm * 64 + mt * 16 + lrow) * 128;
#pragma unroll
    for (int pr = 0; pr < 2; pr++)
        boff[pr] = A_BYTES + (wn * 32 + pr * 16 + lrow) * 128;

    float acc[4][4][4];
#pragma unroll
    for (int i = 0; i < 4; i++)
#pragma unroll
        for (int j = 0; j < 4; j++)
#pragma unroll
            for (int q = 0; q < 4; q++) acc[i][j][q] = 0.f;

    const int NC = K / BKH;

    auto loadc = [&](int c, int slot) {
        const uint32_t sA = sbase + slot * SLOT_BYTES;
        const uint32_t sB = sA + A_BYTES;
        const __half* Ab = A + (size_t)m0 * K + c * BKH;
        const __half* Bb = B + (size_t)n0 * K + c * BKH;
#pragma unroll
        for (int i = 0; i < 4; i++) {
            int idx = tid + i * 256;
            int r = idx >> 3, ch = idx & 7;
            cp16(sA + r * 128 + ((ch ^ (r & 7)) << 4), Ab + (size_t)r * K + ch * 8);
        }
#pragma unroll
        for (int i = 0; i < 4; i++) {
            int idx = tid + i * 256;
            int r = idx >> 3, ch = idx & 7;
            cp16(sB + r * 128 + ((ch ^ (r & 7)) << 4), Bb + (size_t)r * K + ch * 8);
        }
    };

    loadc(0, 0); cp_commit();
    loadc(1, 1); cp_commit();

    int slot = 0;
    for (int c = 0; c < NC; c++) {
        if (c + 2 < NC) cp_wait<1>(); else cp_wait<0>();
        __syncthreads();
        int nslot = slot + 2; if (nslot >= NSLOT) nslot -= NSLOT;
        if (c + 2 < NC) { loadc(c + 2, nslot); cp_commit(); }

        const uint32_t slotb = sbase + slot * SLOT_BYTES;
#pragma unroll
        for (int ks = 0; ks < 4; ks++) {
            const uint32_t cb = (uint32_t)(((2 * ks + lsel) ^ lxor) << 4);
            uint32_t af[4][4];
#pragma unroll
            for (int mt = 0; mt < 4; mt++)
                ldsm4(af[mt][0], af[mt][1], af[mt][2], af[mt][3],
                      slotb + aoff[mt] + cb);
            uint32_t bf[4][2];
#pragma unroll
            for (int pr = 0; pr < 2; pr++) {
                uint32_t r0, r1, r2, r3;
                ldsm4(r0, r1, r2, r3, slotb + boff[pr] + cb);
                bf[2 * pr][0] = r0; bf[2 * pr][1] = r2;
                bf[2 * pr + 1][0] = r1; bf[2 * pr + 1][1] = r3;
            }
#pragma unroll
            for (int mt = 0; mt < 4; mt++)
#pragma unroll
                for (int nt = 0; nt < 4; nt++)
                    mma_f16(acc[mt][nt], af[mt], bf[nt]);
        }
        if (++slot >= NSLOT) slot = 0;
    }

    // epilogue (fp16 out, optional fp16 residual)
#pragma unroll
    for (int mt = 0; mt < 4; mt++) {
        const int row = m0 + wm * 64 + mt * 16 + g;
#pragma unroll
        for (int nt = 0; nt < 4; nt++) {
            const int cc = wn * 32 + nt * 8 + 2 * t;
            float b0 = sbias[cc], b1 = sbias[cc + 1];
            float r00 = acc[mt][nt][0] + b0, r01 = acc[mt][nt][1] + b1;
            float r10 = acc[mt][nt][2] + b0, r11 = acc[mt][nt][3] + b1;
            if (ADDRES) {
                float2 q0 = __half22float2(
                    *(const __half2*)(RresH + (size_t)row * N + n0 + cc));
                float2 q1 = __half22float2(
                    *(const __half2*)(RresH + (size_t)(row + 8) * N + n0 + cc));
                r00 += q0.x; r01 += q0.y; r10 += q1.x; r11 += q1.y;
            }
            if (RELU) {
                r00 = fmaxf(r00, 0.f); r01 = fmaxf(r01, 0.f);
                r10 = fmaxf(r10, 0.f); r11 = fmaxf(r11, 0.f);
            }
            __half2 h0 = __floats2half2_rn(r00, r01);
            __half2 h1 = __floats2half2_rn(r10, r11);
            *(__half2*)(Ch + (size_t)row * N + n0 + cc) = h0;
            *(__half2*)(Ch + (size_t)(row + 8) * N + n0 + cc) = h1;
        }
    }
}

// ============================ attention (R14 winner, unchanged) ==================
#define SSTH2 260
#define S_BYTES (64 * SSTH2 * 4)
#define QOFF S_BYTES
#define KOFF0 (QOFF + 8192)
#define ATTN_SMEM (KOFF0 + 3 * 8192)

__global__ void __launch_bounds__(256, 2) attn_mma(
    const __half* __restrict__ qkvh, __half* __restrict__ oh)
{
    extern __shared__ char smc[];
    __half2* Sh2 = (__half2*)smc;
    const uint32_t sb = smem_u32(smc);

    const int tid = threadIdx.x;
    const int wid = tid >> 5, lane = tid & 31;
    const int g = lane >> 2, t = lane & 3;
    const int wq = wid & 1, wk = wid >> 1;
    const int qt = blockIdx.x, hh = blockIdx.y, gg = blockIdx.z;
    const size_t nb = (size_t)gg * NPG;

    const int lr = tid >> 3, lch = tid & 7;

#pragma unroll
    for (int i = 0; i < 2; i++) {
        int r = lr + i * 32;
        cp16(sb + QOFF + r * 128 + (((uint32_t)lch ^ (r & 7)) << 4),
             qkvh + (nb + qt * 64 + r) * 3072 + hh * 64 + lch * 8);
    }
    cp_commit();
#pragma unroll
    for (int j = 0; j < 2; j++) {
#pragma unroll
        for (int i = 0; i < 2; i++) {
            int r = lr + i * 32;
            cp16(sb + KOFF0 + j * 8192 + r * 128 + (((uint32_t)lch ^ (r & 7)) << 4),
                 qkvh + (nb + j * 64 + r) * 3072 + 1024 + hh * 64 + lch * 8);
        }
        cp_commit();
    }

    cp_wait<1>();
    __syncthreads();

    uint32_t afq[4][2][4];
#pragma unroll
    for (int ks = 0; ks < 4; ks++)
#pragma unroll
        for (int mt = 0; mt < 2; mt++) {
            uint32_t qb = sb + QOFF + (wq * 32 + mt * 16 + g) * 128 + (t << 2);
            uint32_t c0 = (uint32_t)(((2 * ks) ^ g) << 4);
            uint32_t c1 = (uint32_t)(((2 * ks + 1) ^ g) << 4);
            afq[ks][mt][0] = lds32(qb + c0);
            afq[ks][mt][1] = lds32(qb + 8 * 128 + c0);
            afq[ks][mt][2] = lds32(qb + c1);
            afq[ks][mt][3] = lds32(qb + 8 * 128 + c1);
        }

    for (int kt = 0; kt < 8; kt++) {
        if (kt) {
            if (kt + 2 < 8) cp_wait<1>(); else cp_wait<0>();
            __syncthreads();
        }
        if (kt + 2 < 8) {
            int j = (kt + 2) % 3;
#pragma unroll
            for (int i = 0; i < 2; i++) {
                int r = lr + i * 32;
                cp16(sb + KOFF0 + j * 8192 + r * 128 + (((uint32_t)lch ^ (r & 7)) << 4),
                     qkvh + (nb + (kt + 2) * 64 + r) * 3072 + 1024 + hh * 64 + lch * 8);
            }
            cp_commit();
        }
        const uint32_t kb = sb + KOFF0 + (kt % 3) * 8192;

        float sc[2][2][4];
#pragma unroll
        for (int a = 0; a < 2; a++)
#pragma unroll
            for (int b = 0; b < 2; b++)
#pragma unroll
                for (int q = 0; q < 4; q++) sc[a][b][q] = 0.f;
#pragma unroll
        for (int ks = 0; ks < 4; ks++) {
            uint32_t bf[2][2];
#pragma unroll
            for (int nt = 0; nt < 2; nt++) {
                uint32_t base = kb + (wk * 16 + nt * 8 + g) * 128 + (t << 2);
                bf[nt][0] = lds32(base + (uint32_t)(((2 * ks) ^ g) << 4));
                bf[nt][1] = lds32(base + (uint32_t)(((2 * ks + 1) ^ g) << 4));
            }
#pragma unroll
            for (int mt = 0; mt < 2; mt++)
#pragma unroll
                for (int nt = 0; nt < 2; nt++)
                    mma_f16(sc[mt][nt], afq[ks][mt], bf[nt]);
        }
#pragma unroll
        for (int mt = 0; mt < 2; mt++)
#pragma unroll
            for (int nt = 0; nt < 2; nt++) {
                int r = wq * 32 + mt * 16 + g;
                int c2 = kt * 32 + wk * 8 + nt * 4 + t;
                Sh2[r * SSTH2 + c2] =
                    __floats2half2_rn(sc[mt][nt][0] * 0.125f, sc[mt][nt][1] * 0.125f);
                Sh2[(r + 8) * SSTH2 + c2] =
                    __floats2half2_rn(sc[mt][nt][2] * 0.125f, sc[mt][nt][3] * 0.125f);
            }
    }
    __syncthreads();

#pragma unroll
    for (int j = 0; j < 2; j++) {
#pragma unroll
        for (int i = 0; i < 2; i++) {
            int r = lr + i * 32;
            cp16(sb + QOFF + j * 8192 + r * 128 + (((uint32_t)lch ^ (r & 7)) << 4),
                 qkvh + (nb + j * 64 + r) * 3072 + 2048 + hh * 64 + lch * 8);
        }
        cp_commit();
    }

    for (int r = wid; r < 64; r += 8) {
        __half2* row = Sh2 + r * SSTH2;
        float2 v[8];
        float mx = -1e30f;
#pragma unroll
        for (int c = 0; c < 8; c++) {
            v[c] = __half22float2(row[lane + 32 * c]);
            mx = fmaxf(mx, fmaxf(v[c].x, v[c].y));
        }
#pragma unroll
        for (int off = 16; off; off >>= 1)
            mx = fmaxf(mx, __shfl_xor_sync(0xffffffffu, mx, off));
        float sum = 0.f;
#pragma unroll
        for (int c = 0; c < 8; c++) {
            v[c].x = __expf(v[c].x - mx); v[c].y = __expf(v[c].y - mx);
            sum += v[c].x + v[c].y;
        }
#pragma unroll
        for (int off = 16; off; off >>= 1)
            sum += __shfl_xor_sync(0xffffffffu, sum, off);
        float inv = 1.f / sum;
#pragma unroll
        for (int c = 0; c < 8; c++)
            row[lane + 32 * c] = __floats2half2_rn(v[c].x * inv, v[c].y * inv);
    }
    __syncthreads();

    float oacc[2][2][4];
#pragma unroll
    for (int a = 0; a < 2; a++)
#pragma unroll
        for (int b = 0; b < 2; b++)
#pragma unroll
            for (int q = 0; q < 4; q++) oacc[a][b][q] = 0.f;

    const uint32_t* P32 = (const uint32_t*)smc;
    const int lm = lane >> 3, lrr = lane & 7;
    const uint32_t vchunk = (uint32_t)(2 * wk + (lm >> 1));
    const uint32_t vnodeb = (uint32_t)((lm & 1) * 8 + lrr);

    for (int vt = 0; vt < 8; vt++) {
        if (vt + 2 < 8) cp_wait<1>(); else cp_wait<0>();
        __syncthreads();
        if (vt + 2 < 8) {
            int j = (vt + 2) % 3;
#pragma unroll
            for (int i = 0; i < 2; i++) {
                int r = lr + i * 32;
                cp16(sb + QOFF + j * 8192 + r * 128 + (((uint32_t)lch ^ (r & 7)) << 4),
                     qkvh + (nb + (vt + 2) * 64 + r) * 3072 + 2048 + hh * 64 + lch * 8);
            }
            cp_commit();
        }
        const uint32_t vb = sb + QOFF + (vt % 3) * 8192;
#pragma unroll
        for (int ks = 0; ks < 4; ks++) {
            uint32_t af[2][4];
#pragma unroll
            for (int mt = 0; mt < 2; mt++) {
                const uint32_t* p = P32 + (wq * 32 + mt * 16 + g) * SSTH2 +
                                    vt * 32 + ks * 8 + t;
                af[mt][0] = p[0]; af[mt][1] = p[8 * SSTH2];
                af[mt][2] = p[4]; af[mt][3] = p[8 * SSTH2 + 4];
            }
            uint32_t nl = (uint32_t)(ks * 16) + vnodeb;
            uint32_t b0, b1, b2, b3;
            ldsm4t(b0, b1, b2, b3, vb + nl * 128 + ((vchunk ^ lrr) << 4));
            uint32_t bf[2][2] = {{b0, b1}, {b2, b3}};
#pragma unroll
            for (int mt = 0; mt < 2; mt++)
#pragma unroll
                for (int nt = 0; nt < 2; nt++)
                    mma_f16(oacc[mt][nt], af[mt], bf[nt]);
        }
    }

#pragma unroll
    for (int mt = 0; mt < 2; mt++) {
        int r0 = wq * 32 + mt * 16 + g;
#pragma unroll
        for (int nt = 0; nt < 2; nt++) {
            int col = hh * 64 + wk * 16 + nt * 8 + 2 * t;
            size_t base = (nb + qt * 64 + r0) * 1024 + col;
            __half2 h0 = __floats2half2_rn(oacc[mt][nt][0], oacc[mt][nt][1]);
            __half2 h1 = __floats2half2_rn(oacc[mt][nt][2], oacc[mt][nt][3]);
            *(__half2*)(oh + base) = h0;
            *(__half2*)(oh + base + 8 * 1024) = h1;
        }
    }
}

// ---------------- LayerNorm: fp16 input, stats in fp32 ----------------
// OUTF: write fp32 (final) else fp16
template <bool OUTF>
__global__ void __launch_bounds__(256) ln_h(
    const __half* __restrict__ X,
    const float* __restrict__ gamma, const float* __restrict__ beta,
    float* __restrict__ outf, __half* __restrict__ outh)
{
    const int row = blockIdx.x;
    const int tid = threadIdx.x;
    uint2 u = ((const uint2*)(X + (size_t)row * DIM))[tid];
    float2 p0 = __half22float2(*(__half2*)&u.x);
    float2 p1 = __half22float2(*(__half2*)&u.y);
    float4 s = {p0.x, p0.y, p1.x, p1.y};
    float sum = s.x + s.y + s.z + s.w;
    float sq  = s.x * s.x + s.y * s.y + s.z * s.z + s.w * s.w;

    __shared__ float red[16];
#pragma unroll
    for (int off = 16; off; off >>= 1) {
        sum += __shfl_xor_sync(0xffffffffu, sum, off);
        sq  += __shfl_xor_sync(0xffffffffu, sq, off);
    }
    const int warp = tid >> 5, lane = tid & 31;
    if (lane == 0) { red[warp] = sum; red[8 + warp] = sq; }
    __syncthreads();
    sum = 0.f; sq = 0.f;
#pragma unroll
    for (int w = 0; w < 8; w++) { sum += red[w]; sq += red[8 + w]; }

    const float mean = sum * (1.0f / DIM);
    const float var  = sq * (1.0f / DIM) - mean * mean;
    const float inv  = rsqrtf(var + 1e-5f);
    const float4 gm = ((const float4*)gamma)[tid];
    const float4 be = ((const float4*)beta)[tid];
    float4 o;
    o.x = (s.x - mean) * inv * gm.x + be.x;
    o.y = (s.y - mean) * inv * gm.y + be.y;
    o.z = (s.z - mean) * inv * gm.z + be.z;
    o.w = (s.w - mean) * inv * gm.w + be.w;
    if (OUTF) {
        ((float4*)(outf + (size_t)row * DIM))[tid] = o;
    } else {
        __half2 h0 = __floats2half2_rn(o.x, o.y);
        __half2 h1 = __floats2half2_rn(o.z, o.w);
        uint2 w; w.x = *(uint32_t*)&h0; w.y = *(uint32_t*)&h1;
        ((uint2*)(outh + (size_t)row * DIM))[tid] = w;
    }
}

// ---------------- launcher ----------------
extern "C" void kernel_launch(void* const* d_in, const int* in_sizes, int n_in,
                              void* d_out, int out_size)
{
    const float* h     = (const float*)d_in[0];
    const float* w_in  = (const float*)d_in[1];
    const float* b_in  = (const float*)d_in[2];
    const float* w_out = (const float*)d_in[3];
    const float* b_out = (const float*)d_in[4];
    const float* ln1g  = (const float*)d_in[5];
    const float* ln1b  = (const float*)d_in[6];
    const float* ln2g  = (const float*)d_in[7];
    const float* ln2b  = (const float*)d_in[8];
    const float* fw1   = (const float*)d_in[9];
    const float* fb1   = (const float*)d_in[10];
    const float* fw2   = (const float*)d_in[11];
    const float* fb2   = (const float*)d_in[12];
    float* out = (float*)d_out;

    __half *h_h, *qkv_h, *attn_h, *x1_h, *tmp_h, *f1_h, *win_h, *wout_h, *fw1_h, *fw2_h;
    cudaGetSymbolAddress((void**)&h_h,    g_h_h);
    cudaGetSymbolAddress((void**)&qkv_h,  g_qkv_h);
    cudaGetSymbolAddress((void**)&attn_h, g_attn_h);
    cudaGetSymbolAddress((void**)&x1_h,   g_x1_h);
    cudaGetSymbolAddress((void**)&tmp_h,  g_tmp_h);
    cudaGetSymbolAddress((void**)&f1_h,   g_f1_h);
    cudaGetSymbolAddress((void**)&win_h,  g_win_h);
    cudaGetSymbolAddress((void**)&wout_h, g_wout_h);
    cudaGetSymbolAddress((void**)&fw1_h,  g_fw1_h);
    cudaGetSymbolAddress((void**)&fw2_h,  g_fw2_h);

    cudaFuncSetAttribute(gemm_h<false, false>,
                         cudaFuncAttributeMaxDynamicSharedMemorySize, GEMM_SMEM);
    cudaFuncSetAttribute(gemm_h<false, true>,
                         cudaFuncAttributeMaxDynamicSharedMemorySize, GEMM_SMEM);
    cudaFuncSetAttribute(gemm_h<true, false>,
                         cudaFuncAttributeMaxDynamicSharedMemorySize, GEMM_SMEM);
    cudaFuncSetAttribute(attn_mma,
                         cudaFuncAttributeMaxDynamicSharedMemorySize, ATTN_SMEM);

    // 0) fp16 conversions (single launch)
    f32_to_f16_all<<<(CNT + 255) / 256, 256>>>(
        h, h_h, w_in, win_h, w_out, wout_h, fw1, fw1_h, fw2, fw2_h);

    // 1) QKV
    gemm_h<false, false><<<dim3(3 * DIM / BN, T_NODES / BM), 256, GEMM_SMEM>>>(
        h_h, win_h, b_in, qkv_h, nullptr, T_NODES, 3 * DIM, DIM);
    // 2) attention
    attn_mma<<<dim3(8, NHEAD, NGRAPH), 256, ATTN_SMEM>>>(qkv_h, attn_h);
    // 3) out-proj + residual(h_h) -> tmp_h (fp16)
    gemm_h<false, true><<<dim3(DIM / BN, T_NODES / BM), 256, GEMM_SMEM>>>(
        attn_h, wout_h, b_out, tmp_h, h_h, T_NODES, DIM, DIM);
    // 4) x1_h = LN1(tmp_h)  (fp16 out only)
    ln_h<false><<<T_NODES, 256>>>(tmp_h, ln1g, ln1b, nullptr, x1_h);
    // 5) FFN1 + ReLU
    gemm_h<true, false><<<dim3(2 * DIM / BN, T_NODES / BM), 256, GEMM_SMEM>>>(
        x1_h, fw1_h, fb1, f1_h, nullptr, T_NODES, 2 * DIM, DIM);
    // 6) FFN2 + residual(x1_h) -> tmp_h
    gemm_h<false, true><<<dim3(DIM / BN, T_NODES / BM), 256, GEMM_SMEM>>>(
        f1_h, fw2_h, fb2, tmp_h, x1_h, T_NODES, DIM, 2 * DIM);
    // 7) out = LN2(tmp_h)  (fp32 final)
    ln_h<true><<<T_NODES, 256>>>(tmp_h, ln2g, ln2b, out, nullptr);
}

// round 16
// speedup vs baseline: 1.1333x; 1.0729x over previous
#include <cuda_runtime.h>
#include <cuda_fp16.h>
#include <cstdint>
#include <math.h>

#define T_NODES 16384
#define DIM     1024
#define NHEAD   16
#define HD      64
#define NGRAPH  32
#define NPG     512

// ---------------- scratch (device globals) ----------------
__device__ __half g_h_h  [(size_t)T_NODES * DIM];
__device__ __half g_qkv_h[(size_t)T_NODES * 3 * DIM];
__device__ __half g_attn_h[(size_t)T_NODES * DIM];
__device__ __half g_x1_h [(size_t)T_NODES * DIM];
__device__ __half g_tmp_h[(size_t)T_NODES * DIM];
__device__ __half g_f1_h [(size_t)T_NODES * 2 * DIM];
__device__ __half g_win_h [3 * DIM * DIM];
__device__ __half g_wout_h[DIM * DIM];
__device__ __half g_fw1_h [2 * DIM * DIM];
__device__ __half g_fw2_h [2 * DIM * DIM];

// ---------------- helpers ----------------
__device__ __forceinline__ uint32_t smem_u32(const void* p) {
    uint32_t a;
    asm("{ .reg .u64 t; cvta.to.shared.u64 t, %1; cvt.u32.u64 %0, t; }" : "=r"(a) : "l"(p));
    return a;
}
__device__ __forceinline__ void mma_f16(float* c, const uint32_t* a, const uint32_t* b) {
    asm volatile(
        "mma.sync.aligned.m16n8k16.row.col.f32.f16.f16.f32 "
        "{%0,%1,%2,%3}, {%4,%5,%6,%7}, {%8,%9}, {%0,%1,%2,%3};"
        : "+f"(c[0]), "+f"(c[1]), "+f"(c[2]), "+f"(c[3])
        : "r"(a[0]), "r"(a[1]), "r"(a[2]), "r"(a[3]), "r"(b[0]), "r"(b[1]));
}
__device__ __forceinline__ void ldsm4(uint32_t& r0, uint32_t& r1, uint32_t& r2,
                                      uint32_t& r3, uint32_t addr) {
    asm volatile("ldmatrix.sync.aligned.m8n8.x4.shared.b16 {%0,%1,%2,%3}, [%4];"
                 : "=r"(r0), "=r"(r1), "=r"(r2), "=r"(r3) : "r"(addr));
}
__device__ __forceinline__ void ldsm4t(uint32_t& r0, uint32_t& r1, uint32_t& r2,
                                       uint32_t& r3, uint32_t addr) {
    asm volatile("ldmatrix.sync.aligned.m8n8.x4.trans.shared.b16 {%0,%1,%2,%3}, [%4];"
                 : "=r"(r0), "=r"(r1), "=r"(r2), "=r"(r3) : "r"(addr));
}
__device__ __forceinline__ void cp16(uint32_t dst, const void* src) {
    asm volatile("cp.async.cg.shared.global [%0], [%1], 16;" :: "r"(dst), "l"(src));
}
__device__ __forceinline__ void cp_commit() { asm volatile("cp.async.commit_group;"); }
template <int N>
__device__ __forceinline__ void cp_wait() {
    asm volatile("cp.async.wait_group %0;" :: "n"(N));
}

// ---------------- fused fp32 -> fp16 converts (one launch) ----------------
#define CN0 (T_NODES * DIM / 4)
#define CN1 (3 * DIM * DIM / 4)
#define CN2 (DIM * DIM / 4)
#define CN3 (2 * DIM * DIM / 4)
#define CN4 (2 * DIM * DIM / 4)
#define CNT (CN0 + CN1 + CN2 + CN3 + CN4)

__global__ void __launch_bounds__(256) f32_to_f16_all(
    const float* __restrict__ a0, __half* __restrict__ b0,
    const float* __restrict__ a1, __half* __restrict__ b1,
    const float* __restrict__ a2, __half* __restrict__ b2,
    const float* __restrict__ a3, __half* __restrict__ b3,
    const float* __restrict__ a4, __half* __restrict__ b4)
{
    int i = blockIdx.x * 256 + threadIdx.x;
    if (i >= CNT) return;
    const float* s; __half* d; int off;
    if (i < CN0)                       { s = a0; d = b0; off = i; }
    else if (i < CN0 + CN1)            { s = a1; d = b1; off = i - CN0; }
    else if (i < CN0 + CN1 + CN2)      { s = a2; d = b2; off = i - CN0 - CN1; }
    else if (i < CN0 + CN1 + CN2 + CN3){ s = a3; d = b3; off = i - CN0 - CN1 - CN2; }
    else                               { s = a4; d = b4; off = i - CN0 - CN1 - CN2 - CN3; }
    float4 v = ((const float4*)s)[off];
    __half2 x = __floats2half2_rn(v.x, v.y);
    __half2 y = __floats2half2_rn(v.z, v.w);
    uint2 u; u.x = *(uint32_t*)&x; u.y = *(uint32_t*)&y;
    ((uint2*)d)[off] = u;
}

// ============================ fp16 mma GEMM (R15 winner, unchanged) ==========
#define BM 128
#define BN 128
#define BKH 64
#define A_BYTES (BM * 128)
#define B_BYTES (BN * 128)
#define SLOT_BYTES (A_BYTES + B_BYTES)          // 32768
#define NSLOT 3
#define GEMM_SMEM (NSLOT * SLOT_BYTES + 512)    // 98816 -> 2 CTAs/SM

template <bool RELU, bool ADDRES>
__global__ void __launch_bounds__(256, 2) gemm_h(
    const __half* __restrict__ A, const __half* __restrict__ B,
    const float* __restrict__ bias, __half* __restrict__ Ch,
    const __half* __restrict__ RresH, int M, int N, int K)
{
    extern __shared__ char smem[];
    const uint32_t sbase = smem_u32(smem);
    float* sbias = (float*)(smem + NSLOT * SLOT_BYTES);

    const int tid = threadIdx.x;
    const int wid = tid >> 5, lane = tid & 31;
    const int g = lane >> 2, t = lane & 3;
    const int wm = wid & 1, wn = wid >> 1;
    const int m0 = blockIdx.y * BM, n0 = blockIdx.x * BN;

    if (tid < BN) sbias[tid] = bias[n0 + tid];

    const int lrow = lane & 15;
    const int lsel = lane >> 4;
    const int lxor = lane & 7;
    uint32_t aoff[4], boff[2];
#pragma unroll
    for (int mt = 0; mt < 4; mt++)
        aoff[mt] = (wm * 64 + mt * 16 + lrow) * 128;
#pragma unroll
    for (int pr = 0; pr < 2; pr++)
        boff[pr] = A_BYTES + (wn * 32 + pr * 16 + lrow) * 128;

    float acc[4][4][4];
#pragma unroll
    for (int i = 0; i < 4; i++)
#pragma unroll
        for (int j = 0; j < 4; j++)
#pragma unroll
            for (int q = 0; q < 4; q++) acc[i][j][q] = 0.f;

    const int NC = K / BKH;

    auto loadc = [&](int c, int slot) {
        const uint32_t sA = sbase + slot * SLOT_BYTES;
        const uint32_t sB = sA + A_BYTES;
        const __half* Ab = A + (size_t)m0 * K + c * BKH;
        const __half* Bb = B + (size_t)n0 * K + c * BKH;
#pragma unroll
        for (int i = 0; i < 4; i++) {
            int idx = tid + i * 256;
            int r = idx >> 3, ch = idx & 7;
            cp16(sA + r * 128 + ((ch ^ (r & 7)) << 4), Ab + (size_t)r * K + ch * 8);
        }
#pragma unroll
        for (int i = 0; i < 4; i++) {
            int idx = tid + i * 256;
            int r = idx >> 3, ch = idx & 7;
            cp16(sB + r * 128 + ((ch ^ (r & 7)) << 4), Bb + (size_t)r * K + ch * 8);
        }
    };

    loadc(0, 0); cp_commit();
    loadc(1, 1); cp_commit();

    int slot = 0;
    for (int c = 0; c < NC; c++) {
        if (c + 2 < NC) cp_wait<1>(); else cp_wait<0>();
        __syncthreads();
        int nslot = slot + 2; if (nslot >= NSLOT) nslot -= NSLOT;
        if (c + 2 < NC) { loadc(c + 2, nslot); cp_commit(); }

        const uint32_t slotb = sbase + slot * SLOT_BYTES;
#pragma unroll
        for (int ks = 0; ks < 4; ks++) {
            const uint32_t cb = (uint32_t)(((2 * ks + lsel) ^ lxor) << 4);
            uint32_t af[4][4];
#pragma unroll
            for (int mt = 0; mt < 4; mt++)
                ldsm4(af[mt][0], af[mt][1], af[mt][2], af[mt][3],
                      slotb + aoff[mt] + cb);
            uint32_t bf[4][2];
#pragma unroll
            for (int pr = 0; pr < 2; pr++) {
                uint32_t r0, r1, r2, r3;
                ldsm4(r0, r1, r2, r3, slotb + boff[pr] + cb);
                bf[2 * pr][0] = r0; bf[2 * pr][1] = r2;
                bf[2 * pr + 1][0] = r1; bf[2 * pr + 1][1] = r3;
            }
#pragma unroll
            for (int mt = 0; mt < 4; mt++)
#pragma unroll
                for (int nt = 0; nt < 4; nt++)
                    mma_f16(acc[mt][nt], af[mt], bf[nt]);
        }
        if (++slot >= NSLOT) slot = 0;
    }

    // epilogue (fp16 out, optional fp16 residual)
#pragma unroll
    for (int mt = 0; mt < 4; mt++) {
        const int row = m0 + wm * 64 + mt * 16 + g;
#pragma unroll
        for (int nt = 0; nt < 4; nt++) {
            const int cc = wn * 32 + nt * 8 + 2 * t;
            float b0 = sbias[cc], b1 = sbias[cc + 1];
            float r00 = acc[mt][nt][0] + b0, r01 = acc[mt][nt][1] + b1;
            float r10 = acc[mt][nt][2] + b0, r11 = acc[mt][nt][3] + b1;
            if (ADDRES) {
                float2 q0 = __half22float2(
                    *(const __half2*)(RresH + (size_t)row * N + n0 + cc));
                float2 q1 = __half22float2(
                    *(const __half2*)(RresH + (size_t)(row + 8) * N + n0 + cc));
                r00 += q0.x; r01 += q0.y; r10 += q1.x; r11 += q1.y;
            }
            if (RELU) {
                r00 = fmaxf(r00, 0.f); r01 = fmaxf(r01, 0.f);
                r10 = fmaxf(r10, 0.f); r11 = fmaxf(r11, 0.f);
            }
            __half2 h0 = __floats2half2_rn(r00, r01);
            __half2 h1 = __floats2half2_rn(r10, r11);
            *(__half2*)(Ch + (size_t)row * N + n0 + cc) = h0;
            *(__half2*)(Ch + (size_t)(row + 8) * N + n0 + cc) = h1;
        }
    }
}

// ============================ FlashAttention kernel ============================
// CTA: 128-row q-block x (head, graph). 8 warps, warp owns 16 q rows x all keys.
// S never in smem: QK accum -> fp16 P frags in regs -> PV mma. Online softmax.
#define AST_K 8192
#define AST   16384                   // stage = K tile + V tile
#define ASOFF 16384                   // Q tile occupies [0, 16384)
#define ATTN_SMEM (16384 + 3 * AST)   // 65536 -> 2 CTAs/SM

__global__ void __launch_bounds__(256, 2) attn_flash(
    const __half* __restrict__ qkvh, __half* __restrict__ oh)
{
    extern __shared__ char smc[];
    const uint32_t sb = smem_u32(smc);

    const int tid = threadIdx.x;
    const int w = tid >> 5, lane = tid & 31;
    const int g = lane >> 2, t = lane & 3;
    const int qt = blockIdx.x, hh = blockIdx.y, gg = blockIdx.z;
    const size_t nb = (size_t)gg * NPG;
    const int qrow0 = qt * 128;

    const int lr = tid >> 3, lch = tid & 7;

    // issue Q tile (128 rows) -- group 0
#pragma unroll
    for (int i = 0; i < 4; i++) {
        int r = lr + i * 32;
        cp16(sb + r * 128 + (((uint32_t)lch ^ (r & 7)) << 4),
             qkvh + (nb + qrow0 + r) * 3072 + hh * 64 + lch * 8);
    }
    cp_commit();
    // issue stages 0,1 (K+V paired) -- groups 1,2
#pragma unroll
    for (int j = 0; j < 2; j++) {
#pragma unroll
        for (int i = 0; i < 2; i++) {
            int r = lr + i * 32;
            cp16(sb + ASOFF + j * AST + r * 128 + (((uint32_t)lch ^ (r & 7)) << 4),
                 qkvh + (nb + j * 64 + r) * 3072 + 1024 + hh * 64 + lch * 8);
        }
#pragma unroll
        for (int i = 0; i < 2; i++) {
            int r = lr + i * 32;
            cp16(sb + ASOFF + j * AST + AST_K + r * 128 + (((uint32_t)lch ^ (r & 7)) << 4),
                 qkvh + (nb + j * 64 + r) * 3072 + 2048 + hh * 64 + lch * 8);
        }
        cp_commit();
    }

    cp_wait<2>();      // Q ready
    __syncthreads();

    // hoist stationary Q fragments (warp rows w*16 + lrow)
    const int lrow = lane & 15;
    const int lsel = lane >> 4;
    const int lxor = lane & 7;
    const uint32_t qaddr = sb + (w * 16 + lrow) * 128;
    uint32_t afq[4][4];
#pragma unroll
    for (int ks = 0; ks < 4; ks++)
        ldsm4(afq[ks][0], afq[ks][1], afq[ks][2], afq[ks][3],
              qaddr + (uint32_t)(((2 * ks + lsel) ^ lxor) << 4));

    uint32_t koff[4];
#pragma unroll
    for (int pr = 0; pr < 4; pr++)
        koff[pr] = (pr * 16 + lrow) * 128;

    const int lm = lane >> 3, lrr = lane & 7;
    const uint32_t vnodeb = (uint32_t)((lm & 1) * 8 + lrr);

    float Oa[8][4];
#pragma unroll
    for (int i = 0; i < 8; i++)
#pragma unroll
        for (int q = 0; q < 4; q++) Oa[i][q] = 0.f;
    float m0 = -1e30f, m1 = -1e30f, l0 = 0.f, l1 = 0.f;

    for (int kt = 0; kt < 8; kt++) {
        if (kt + 2 < 8) cp_wait<1>(); else cp_wait<0>();
        __syncthreads();
        if (kt + 2 < 8) {
            int j = (kt + 2) % 3;
#pragma unroll
            for (int i = 0; i < 2; i++) {
                int r = lr + i * 32;
                cp16(sb + ASOFF + j * AST + r * 128 + (((uint32_t)lch ^ (r & 7)) << 4),
                     qkvh + (nb + (kt + 2) * 64 + r) * 3072 + 1024 + hh * 64 + lch * 8);
            }
#pragma unroll
            for (int i = 0; i < 2; i++) {
                int r = lr + i * 32;
                cp16(sb + ASOFF + j * AST + AST_K + r * 128 + (((uint32_t)lch ^ (r & 7)) << 4),
                     qkvh + (nb + (kt + 2) * 64 + r) * 3072 + 2048 + hh * 64 + lch * 8);
            }
            cp_commit();
        }
        const uint32_t kb = sb + ASOFF + (kt % 3) * AST;

        // ---- QK^T: 16 q rows x 64 keys ----
        float sc[8][4];
#pragma unroll
        for (int i = 0; i < 8; i++)
#pragma unroll
            for (int q = 0; q < 4; q++) sc[i][q] = 0.f;
#pragma unroll
        for (int ks = 0; ks < 4; ks++) {
            const uint32_t cb = (uint32_t)(((2 * ks + lsel) ^ lxor) << 4);
            uint32_t bf[8][2];
#pragma unroll
            for (int pr = 0; pr < 4; pr++) {
                uint32_t r0, r1, r2, r3;
                ldsm4(r0, r1, r2, r3, kb + koff[pr] + cb);
                bf[2 * pr][0] = r0; bf[2 * pr][1] = r2;
                bf[2 * pr + 1][0] = r1; bf[2 * pr + 1][1] = r3;
            }
#pragma unroll
            for (int nt = 0; nt < 8; nt++)
                mma_f16(sc[nt], afq[ks], bf[nt]);
        }

        // ---- online softmax update ----
        float rm0 = -1e30f, rm1 = -1e30f;
#pragma unroll
        for (int nt = 0; nt < 8; nt++) {
            rm0 = fmaxf(rm0, fmaxf(sc[nt][0], sc[nt][1]));
            rm1 = fmaxf(rm1, fmaxf(sc[nt][2], sc[nt][3]));
        }
        rm0 = fmaxf(rm0, __shfl_xor_sync(0xffffffffu, rm0, 1));
        rm0 = fmaxf(rm0, __shfl_xor_sync(0xffffffffu, rm0, 2));
        rm1 = fmaxf(rm1, __shfl_xor_sync(0xffffffffu, rm1, 1));
        rm1 = fmaxf(rm1, __shfl_xor_sync(0xffffffffu, rm1, 2));
        const float m0n = fmaxf(m0, rm0 * 0.125f);
        const float m1n = fmaxf(m1, rm1 * 0.125f);
        const float c0 = __expf(m0 - m0n), c1 = __expf(m1 - m1n);
#pragma unroll
        for (int i = 0; i < 8; i++) {
            Oa[i][0] *= c0; Oa[i][1] *= c0;
            Oa[i][2] *= c1; Oa[i][3] *= c1;
        }
        l0 *= c0; l1 *= c1;
        m0 = m0n; m1 = m1n;

        // P = exp(s*0.125 - m) as fp16 A-fragments
        uint32_t ap[4][4];
        float s0 = 0.f, s1 = 0.f;
#pragma unroll
        for (int j = 0; j < 4; j++) {
            float p00 = __expf(sc[2 * j][0] * 0.125f - m0n);
            float p01 = __expf(sc[2 * j][1] * 0.125f - m0n);
            float p02 = __expf(sc[2 * j][2] * 0.125f - m1n);
            float p03 = __expf(sc[2 * j][3] * 0.125f - m1n);
            float p10 = __expf(sc[2 * j + 1][0] * 0.125f - m0n);
            float p11 = __expf(sc[2 * j + 1][1] * 0.125f - m0n);
            float p12 = __expf(sc[2 * j + 1][2] * 0.125f - m1n);
            float p13 = __expf(sc[2 * j + 1][3] * 0.125f - m1n);
            s0 += p00 + p01 + p10 + p11;
            s1 += p02 + p03 + p12 + p13;
            __half2 h;
            h = __floats2half2_rn(p00, p01); ap[j][0] = *(uint32_t*)&h;
            h = __floats2half2_rn(p02, p03); ap[j][1] = *(uint32_t*)&h;
            h = __floats2half2_rn(p10, p11); ap[j][2] = *(uint32_t*)&h;
            h = __floats2half2_rn(p12, p13); ap[j][3] = *(uint32_t*)&h;
        }
        l0 += s0; l1 += s1;

        // ---- P @ V ----
        const uint32_t vb = kb + AST_K;
#pragma unroll
        for (int j = 0; j < 4; j++) {
            const uint32_t nl = (uint32_t)(j * 16) + vnodeb;
#pragma unroll
            for (int dd = 0; dd < 4; dd++) {
                const uint32_t vchunk = (uint32_t)(2 * dd + (lm >> 1));
                uint32_t b0, b1, b2, b3;
                ldsm4t(b0, b1, b2, b3, vb + nl * 128 + ((vchunk ^ lrr) << 4));
                uint32_t bfa[2] = {b0, b1}, bfb[2] = {b2, b3};
                mma_f16(Oa[2 * dd], ap[j], bfa);
                mma_f16(Oa[2 * dd + 1], ap[j], bfb);
            }
        }
    }

    // ---- epilogue: normalize and write ----
    l0 += __shfl_xor_sync(0xffffffffu, l0, 1);
    l0 += __shfl_xor_sync(0xffffffffu, l0, 2);
    l1 += __shfl_xor_sync(0xffffffffu, l1, 1);
    l1 += __shfl_xor_sync(0xffffffffu, l1, 2);
    const float inv0 = 1.f / l0, inv1 = 1.f / l1;
    const size_t rowg = (nb + qrow0 + w * 16 + g) * 1024 + hh * 64;
#pragma unroll
    for (int ntd = 0; ntd < 8; ntd++) {
        int col = ntd * 8 + 2 * t;
        __half2 h0 = __floats2half2_rn(Oa[ntd][0] * inv0, Oa[ntd][1] * inv0);
        __half2 h1 = __floats2half2_rn(Oa[ntd][2] * inv1, Oa[ntd][3] * inv1);
        *(__half2*)(oh + rowg + col) = h0;
        *(__half2*)(oh + rowg + 8 * 1024 + col) = h1;
    }
}

// ---------------- LayerNorm: fp16 input, stats in fp32 ----------------
template <bool OUTF>
__global__ void __launch_bounds__(256) ln_h(
    const __half* __restrict__ X,
    const float* __restrict__ gamma, const float* __restrict__ beta,
    float* __restrict__ outf, __half* __restrict__ outh)
{
    const int row = blockIdx.x;
    const int tid = threadIdx.x;
    uint2 u = ((const uint2*)(X + (size_t)row * DIM))[tid];
    float2 p0 = __half22float2(*(__half2*)&u.x);
    float2 p1 = __half22float2(*(__half2*)&u.y);
    float4 s = {p0.x, p0.y, p1.x, p1.y};
    float sum = s.x + s.y + s.z + s.w;
    float sq  = s.x * s.x + s.y * s.y + s.z * s.z + s.w * s.w;

    __shared__ float red[16];
#pragma unroll
    for (int off = 16; off; off >>= 1) {
        sum += __shfl_xor_sync(0xffffffffu, sum, off);
        sq  += __shfl_xor_sync(0xffffffffu, sq, off);
    }
    const int warp = tid >> 5, lane = tid & 31;
    if (lane == 0) { red[warp] = sum; red[8 + warp] = sq; }
    __syncthreads();
    sum = 0.f; sq = 0.f;
#pragma unroll
    for (int w = 0; w < 8; w++) { sum += red[w]; sq += red[8 + w]; }

    const float mean = sum * (1.0f / DIM);
    const float var  = sq * (1.0f / DIM) - mean * mean;
    const float inv  = rsqrtf(var + 1e-5f);
    const float4 gm = ((const float4*)gamma)[tid];
    const float4 be = ((const float4*)beta)[tid];
    float4 o;
    o.x = (s.x - mean) * inv * gm.x + be.x;
    o.y = (s.y - mean) * inv * gm.y + be.y;
    o.z = (s.z - mean) * inv * gm.z + be.z;
    o.w = (s.w - mean) * inv * gm.w + be.w;
    if (OUTF) {
        ((float4*)(outf + (size_t)row * DIM))[tid] = o;
    } else {
        __half2 h0 = __floats2half2_rn(o.x, o.y);
        __half2 h1 = __floats2half2_rn(o.z, o.w);
        uint2 w2; w2.x = *(uint32_t*)&h0; w2.y = *(uint32_t*)&h1;
        ((uint2*)(outh + (size_t)row * DIM))[tid] = w2;
    }
}

// ---------------- launcher ----------------
extern "C" void kernel_launch(void* const* d_in, const int* in_sizes, int n_in,
                              void* d_out, int out_size)
{
    const float* h     = (const float*)d_in[0];
    const float* w_in  = (const float*)d_in[1];
    const float* b_in  = (const float*)d_in[2];
    const float* w_out = (const float*)d_in[3];
    const float* b_out = (const float*)d_in[4];
    const float* ln1g  = (const float*)d_in[5];
    const float* ln1b  = (const float*)d_in[6];
    const float* ln2g  = (const float*)d_in[7];
    const float* ln2b  = (const float*)d_in[8];
    const float* fw1   = (const float*)d_in[9];
    const float* fb1   = (const float*)d_in[10];
    const float* fw2   = (const float*)d_in[11];
    const float* fb2   = (const float*)d_in[12];
    float* out = (float*)d_out;

    __half *h_h, *qkv_h, *attn_h, *x1_h, *tmp_h, *f1_h, *win_h, *wout_h, *fw1_h, *fw2_h;
    cudaGetSymbolAddress((void**)&h_h,    g_h_h);
    cudaGetSymbolAddress((void**)&qkv_h,  g_qkv_h);
    cudaGetSymbolAddress((void**)&attn_h, g_attn_h);
    cudaGetSymbolAddress((void**)&x1_h,   g_x1_h);
    cudaGetSymbolAddress((void**)&tmp_h,  g_tmp_h);
    cudaGetSymbolAddress((void**)&f1_h,   g_f1_h);
    cudaGetSymbolAddress((void**)&win_h,  g_win_h);
    cudaGetSymbolAddress((void**)&wout_h, g_wout_h);
    cudaGetSymbolAddress((void**)&fw1_h,  g_fw1_h);
    cudaGetSymbolAddress((void**)&fw2_h,  g_fw2_h);

    cudaFuncSetAttribute(gemm_h<false, false>,
                         cudaFuncAttributeMaxDynamicSharedMemorySize, GEMM_SMEM);
    cudaFuncSetAttribute(gemm_h<false, true>,
                         cudaFuncAttributeMaxDynamicSharedMemorySize, GEMM_SMEM);
    cudaFuncSetAttribute(gemm_h<true, false>,
                         cudaFuncAttributeMaxDynamicSharedMemorySize, GEMM_SMEM);
    cudaFuncSetAttribute(attn_flash,
                         cudaFuncAttributeMaxDynamicSharedMemorySize, ATTN_SMEM);

    // 0) fp16 conversions (single launch)
    f32_to_f16_all<<<(CNT + 255) / 256, 256>>>(
        h, h_h, w_in, win_h, w_out, wout_h, fw1, fw1_h, fw2, fw2_h);

    // 1) QKV
    gemm_h<false, false><<<dim3(3 * DIM / BN, T_NODES / BM), 256, GEMM_SMEM>>>(
        h_h, win_h, b_in, qkv_h, nullptr, T_NODES, 3 * DIM, DIM);
    // 2) attention (flash)
    attn_flash<<<dim3(4, NHEAD, NGRAPH), 256, ATTN_SMEM>>>(qkv_h, attn_h);
    // 3) out-proj + residual(h_h) -> tmp_h
    gemm_h<false, true><<<dim3(DIM / BN, T_NODES / BM), 256, GEMM_SMEM>>>(
        attn_h, wout_h, b_out, tmp_h, h_h, T_NODES, DIM, DIM);
    // 4) x1_h = LN1(tmp_h)
    ln_h<false><<<T_NODES, 256>>>(tmp_h, ln1g, ln1b, nullptr, x1_h);
    // 5) FFN1 + ReLU
    gemm_h<true, false><<<dim3(2 * DIM / BN, T_NODES / BM), 256, GEMM_SMEM>>>(
        x1_h, fw1_h, fb1, f1_h, nullptr, T_NODES, 2 * DIM, DIM);
    // 6) FFN2 + residual(x1_h) -> tmp_h
    gemm_h<false, true><<<dim3(DIM / BN, T_NODES / BM), 256, GEMM_SMEM>>>(
        f1_h, fw2_h, fb2, tmp_h, x1_h, T_NODES, DIM, 2 * DIM);
    // 7) out = LN2(tmp_h)
    ln_h<true><<<T_NODES, 256>>>(tmp_h, ln2g, ln2b, out, nullptr);
}